// round 1
// baseline (speedup 1.0000x reference)
#include <cuda_runtime.h>

// ---------------------------------------------------------------------------
// GAT (3 layers) over N=50000 nodes, E=800000 edges, D=64 per head.
// Scratch buffers as device globals (no allocation allowed).
// ---------------------------------------------------------------------------

#define NMAX 50000
#define EMAX 800000

__device__ float    g_hA[NMAX * 128];   // ping
__device__ float    g_hB[NMAX * 128];   // pong
__device__ float    g_fh[NMAX * 128];   // h @ W
__device__ float    g_el[NMAX * 2];
__device__ float    g_er[NMAX * 2];
__device__ unsigned g_m [NMAX * 2];     // encoded segment max
__device__ float    g_den[NMAX * 2];    // softmax denominator

// Order-preserving float <-> unsigned encoding (for atomicMax on floats,
// including negatives).
__device__ __forceinline__ unsigned fenc(float f) {
    unsigned u = __float_as_uint(f);
    return (u & 0x80000000u) ? ~u : (u | 0x80000000u);
}
__device__ __forceinline__ float fdec(unsigned u) {
    return __uint_as_float((u & 0x80000000u) ? (u & 0x7FFFFFFFu) : ~u);
}

__device__ __forceinline__ float lrelu(float v) {
    return v > 0.f ? v : 0.2f * v;
}

// ---------------------------------------------------------------------------
// Embedding lookup: h[n,d] = emb[features[n], d] * fv[n]   (row 0 of [8,N])
// ---------------------------------------------------------------------------
__global__ void k_embed(const int* __restrict__ feats, const float* __restrict__ fv,
                        const float* __restrict__ emb, float* __restrict__ h, int N) {
    int i = blockIdx.x * blockDim.x + threadIdx.x;
    if (i >= N * 64) return;
    int n = i >> 6, d = i & 63;
    h[i] = emb[(long long)feats[n] * 64 + d] * fv[n];
}

// ---------------------------------------------------------------------------
// GEMM: out[N,O] = A[N,K] @ W[K,O] (+bias) (+addsrc). blockDim.x == O (64/128).
// Block handles 32 rows.
// ---------------------------------------------------------------------------
__global__ void k_gemm(const float* __restrict__ A, const float* __restrict__ W,
                       const float* __restrict__ bias, const float* __restrict__ addsrc,
                       float* __restrict__ out, int N, int K, int O) {
    __shared__ float Ws[32][128];
    __shared__ float Hs[32][33];
    int tid  = threadIdx.x;
    int row0 = blockIdx.x * 32;

    float acc[32];
#pragma unroll
    for (int r = 0; r < 32; r++) acc[r] = 0.f;

    for (int kt = 0; kt < K; kt += 32) {
#pragma unroll
        for (int k = 0; k < 32; k++) Ws[k][tid] = W[(kt + k) * O + tid];
        for (int i = tid; i < 32 * 32; i += O) {
            int r = i >> 5, c = i & 31;
            int row = row0 + r;
            Hs[r][c] = (row < N) ? A[row * K + kt + c] : 0.f;
        }
        __syncthreads();
#pragma unroll 4
        for (int c = 0; c < 32; c++) {
            float w = Ws[c][tid];
#pragma unroll
            for (int r = 0; r < 32; r++) acc[r] += Hs[r][c] * w;
        }
        __syncthreads();
    }

    float b = bias ? bias[tid] : 0.f;
    for (int r = 0; r < 32; r++) {
        int row = row0 + r;
        if (row < N) {
            float v = acc[r] + b;
            if (addsrc) v += addsrc[row * O + tid];
            out[row * O + tid] = v;
        }
    }
}

// ---------------------------------------------------------------------------
// Attention scores: el[n,h] = <fh[n,h,:], al[h,:]>, er likewise. Warp per node.
// ---------------------------------------------------------------------------
__global__ void k_scores(const float* __restrict__ fh, const float* __restrict__ al,
                         const float* __restrict__ ar, float* __restrict__ el,
                         float* __restrict__ er, int N, int H) {
    int gt = blockIdx.x * blockDim.x + threadIdx.x;
    int n = gt >> 5, lane = gt & 31;
    if (n >= N) return;
    for (int h = 0; h < H; h++) {
        float2 v = *(const float2*)&fh[(n * H + h) * 64 + lane * 2];
        float2 a = *(const float2*)&al[h * 64 + lane * 2];
        float2 b = *(const float2*)&ar[h * 64 + lane * 2];
        float sl = v.x * a.x + v.y * a.y;
        float sr = v.x * b.x + v.y * b.y;
#pragma unroll
        for (int o = 16; o > 0; o >>= 1) {
            sl += __shfl_xor_sync(0xffffffffu, sl, o);
            sr += __shfl_xor_sync(0xffffffffu, sr, o);
        }
        if (lane == 0) { el[n * H + h] = sl; er[n * H + h] = sr; }
    }
}

// ---------------------------------------------------------------------------
// Reset max/den buffers
// ---------------------------------------------------------------------------
__global__ void k_init(unsigned* __restrict__ m, float* __restrict__ den, int n) {
    int i = blockIdx.x * blockDim.x + threadIdx.x;
    if (i < n) { m[i] = 0u; den[i] = 0.f; }
}

// ---------------------------------------------------------------------------
// Seed output accumulator with bias (+ optional residual)
// ---------------------------------------------------------------------------
__global__ void k_seed(float* __restrict__ out, const float* __restrict__ bias,
                       const float* __restrict__ addsrc, int N, int O) {
    int i = blockIdx.x * blockDim.x + threadIdx.x;
    if (i >= N * O) return;
    float v = bias[i & (O - 1)];
    if (addsrc) v += addsrc[i];
    out[i] = v;
}

// ---------------------------------------------------------------------------
// Edge pass 1: segment max of leaky_relu(el[src]+er[dst]) grouped by dst
// ---------------------------------------------------------------------------
__global__ void k_emax(const int* __restrict__ src, const int* __restrict__ dst,
                       const float* __restrict__ el, const float* __restrict__ er,
                       unsigned* __restrict__ m, int E, int H) {
    int i = blockIdx.x * blockDim.x + threadIdx.x;
    if (i >= E * H) return;
    int e = i / H, h = i - e * H;
    int s = src[e], t = dst[e];
    float v = lrelu(el[s * H + h] + er[t * H + h]);
    atomicMax(&m[t * H + h], fenc(v));
}

// ---------------------------------------------------------------------------
// Edge pass 2: denominator sums
// ---------------------------------------------------------------------------
__global__ void k_eden(const int* __restrict__ src, const int* __restrict__ dst,
                       const float* __restrict__ el, const float* __restrict__ er,
                       const unsigned* __restrict__ m, float* __restrict__ den,
                       int E, int H) {
    int i = blockIdx.x * blockDim.x + threadIdx.x;
    if (i >= E * H) return;
    int e = i / H, h = i - e * H;
    int s = src[e], t = dst[e];
    float v = lrelu(el[s * H + h] + er[t * H + h]);
    float ex = __expf(v - fdec(m[t * H + h]));
    atomicAdd(&den[t * H + h], ex);
}

// ---------------------------------------------------------------------------
// Edge pass 3: out[dst,h,:] += alpha * fh[src,h,:]. One warp per (edge,head),
// each lane handles 2 consecutive features.
// ---------------------------------------------------------------------------
__global__ void k_eacc(const int* __restrict__ src, const int* __restrict__ dst,
                       const float* __restrict__ el, const float* __restrict__ er,
                       const unsigned* __restrict__ m, const float* __restrict__ den,
                       const float* __restrict__ fh, float* __restrict__ out,
                       int E, int H) {
    int gt = blockIdx.x * blockDim.x + threadIdx.x;
    int w = gt >> 5, lane = gt & 31;
    if (w >= E * H) return;
    int e = w / H, h = w - e * H;
    int s = src[e], t = dst[e];
    float v = lrelu(el[s * H + h] + er[t * H + h]);
    float alpha = __expf(v - fdec(m[t * H + h])) / fmaxf(den[t * H + h], 1e-9f);
    float2 f = *(const float2*)&fh[(s * H + h) * 64 + lane * 2];
    float* o = &out[(t * H + h) * 64 + lane * 2];
    atomicAdd(o,     alpha * f.x);
    atomicAdd(o + 1, alpha * f.y);
}

// ---------------------------------------------------------------------------
// ELU in place
// ---------------------------------------------------------------------------
__global__ void k_elu(float* __restrict__ x, int n) {
    int i = blockIdx.x * blockDim.x + threadIdx.x;
    if (i < n) {
        float v = x[i];
        x[i] = v > 0.f ? v : (__expf(v) - 1.f);
    }
}

// ---------------------------------------------------------------------------
// Launch
// ---------------------------------------------------------------------------
extern "C" void kernel_launch(void* const* d_in, const int* in_sizes, int n_in,
                              void* d_out, int out_size) {
    const int*   feats = (const int*)  d_in[0];
    const float* fv    = (const float*)d_in[1];
    const int*   src   = (const int*)  d_in[2];
    const int*   dst   = (const int*)  d_in[3];
    const float* emb   = (const float*)d_in[4];
    const float* W0    = (const float*)d_in[5];
    const float* al0   = (const float*)d_in[6];
    const float* ar0   = (const float*)d_in[7];
    const float* b0    = (const float*)d_in[8];
    const float* W1    = (const float*)d_in[9];
    const float* al1   = (const float*)d_in[10];
    const float* ar1   = (const float*)d_in[11];
    const float* b1    = (const float*)d_in[12];
    const float* W2    = (const float*)d_in[13];
    const float* al2   = (const float*)d_in[14];
    const float* ar2   = (const float*)d_in[15];
    const float* b2    = (const float*)d_in[16];
    const float* resW2 = (const float*)d_in[17];
    float* out = (float*)d_out;

    const int N = in_sizes[0] / 8;   // features: [8, N]
    const int E = in_sizes[2];       // src: [E]

    float *hA, *hB, *fh, *el, *er, *den;
    unsigned* m;
    cudaGetSymbolAddress((void**)&hA,  g_hA);
    cudaGetSymbolAddress((void**)&hB,  g_hB);
    cudaGetSymbolAddress((void**)&fh,  g_fh);
    cudaGetSymbolAddress((void**)&el,  g_el);
    cudaGetSymbolAddress((void**)&er,  g_er);
    cudaGetSymbolAddress((void**)&m,   g_m);
    cudaGetSymbolAddress((void**)&den, g_den);

    const int TB = 256;
    int gemmBlocks = (N + 31) / 32;
    int scoreBlocks = (N * 32 + TB - 1) / TB;

    // Embedding -> hA [N,64]
    k_embed<<<(N * 64 + TB - 1) / TB, TB>>>(feats, fv, emb, hA, N);

    // ---------------- Layer 0: K=64 -> H=2,D=64 (O=128), out -> hB ----------
    {
        int H = 2, O = 128;
        k_gemm<<<gemmBlocks, O>>>(hA, W0, nullptr, nullptr, fh, N, 64, O);
        k_scores<<<scoreBlocks, TB>>>(fh, al0, ar0, el, er, N, H);
        k_init<<<(N * H + TB - 1) / TB, TB>>>(m, den, N * H);
        k_seed<<<(N * O + TB - 1) / TB, TB>>>(hB, b0, nullptr, N, O);
        k_emax<<<(E * H + TB - 1) / TB, TB>>>(src, dst, el, er, m, E, H);
        k_eden<<<(E * H + TB - 1) / TB, TB>>>(src, dst, el, er, m, den, E, H);
        long long accT = (long long)E * H * 32;
        k_eacc<<<(int)((accT + TB - 1) / TB), TB>>>(src, dst, el, er, m, den, fh, hB, E, H);
        k_elu<<<(N * O + TB - 1) / TB, TB>>>(hB, N * O);
    }

    // ---------------- Layer 1: K=128 -> H=2,D=64 (O=128), residual=hB, out -> hA
    {
        int H = 2, O = 128;
        k_gemm<<<gemmBlocks, O>>>(hB, W1, nullptr, nullptr, fh, N, 128, O);
        k_scores<<<scoreBlocks, TB>>>(fh, al1, ar1, el, er, N, H);
        k_init<<<(N * H + TB - 1) / TB, TB>>>(m, den, N * H);
        k_seed<<<(N * O + TB - 1) / TB, TB>>>(hA, b1, hB, N, O);
        k_emax<<<(E * H + TB - 1) / TB, TB>>>(src, dst, el, er, m, E, H);
        k_eden<<<(E * H + TB - 1) / TB, TB>>>(src, dst, el, er, m, den, E, H);
        long long accT = (long long)E * H * 32;
        k_eacc<<<(int)((accT + TB - 1) / TB), TB>>>(src, dst, el, er, m, den, fh, hA, E, H);
        k_elu<<<(N * O + TB - 1) / TB, TB>>>(hA, N * O);
    }

    // ---------------- Layer 2: K=128 -> H=1,D=64 (O=64), proj residual, out -> d_out
    {
        int H = 1, O = 64;
        k_gemm<<<gemmBlocks, O>>>(hA, W2, nullptr, nullptr, fh, N, 128, O);
        k_scores<<<scoreBlocks, TB>>>(fh, al2, ar2, el, er, N, H);
        k_init<<<(N * H + TB - 1) / TB, TB>>>(m, den, N * H);
        // seed d_out = hA @ resW2 + b2   (projected residual + bias)
        k_gemm<<<gemmBlocks, O>>>(hA, resW2, b2, nullptr, out, N, 128, O);
        k_emax<<<(E * H + TB - 1) / TB, TB>>>(src, dst, el, er, m, E, H);
        k_eden<<<(E * H + TB - 1) / TB, TB>>>(src, dst, el, er, m, den, E, H);
        long long accT = (long long)E * H * 32;
        k_eacc<<<(int)((accT + TB - 1) / TB), TB>>>(src, dst, el, er, m, den, fh, out, E, H);
        // no activation; H=1 mean == identity
    }
}

// round 2
// speedup vs baseline: 1.8394x; 1.8394x over previous
#include <cuda_runtime.h>
#include <math_constants.h>

// ---------------------------------------------------------------------------
// 3-layer GAT, N=50000 nodes, E=800000 edges, D=64 per head.
// Strategy: build dst-CSR once per launch, then one fused
// (edge-softmax + aggregate + bias + residual + ELU) kernel per layer.
// ---------------------------------------------------------------------------

#define NMAX 50000
#define EMAX 800000

__device__ float g_hA[NMAX * 128];
__device__ float g_hB[NMAX * 128];
__device__ float g_fh[NMAX * 128];
__device__ float g_el[NMAX * 2];
__device__ float g_er[NMAX * 2];
__device__ int   g_row[NMAX + 1];
__device__ int   g_cur[NMAX];
__device__ int   g_col[EMAX];

// ---------------------------------------------------------------------------
// Embedding lookup: h[n,d] = emb[features[0,n], d] * fv[0,n]
// ---------------------------------------------------------------------------
__global__ void k_embed(const int* __restrict__ feats, const float* __restrict__ fv,
                        const float* __restrict__ emb, float* __restrict__ h, int N) {
    int i = blockIdx.x * blockDim.x + threadIdx.x;
    if (i >= N * 64) return;
    int n = i >> 6, d = i & 63;
    h[i] = emb[(long long)feats[n] * 64 + d] * fv[n];
}

// ---------------------------------------------------------------------------
// CSR build
// ---------------------------------------------------------------------------
__global__ void k_zero(int* __restrict__ c, int n) {
    int i = blockIdx.x * blockDim.x + threadIdx.x;
    if (i < n) c[i] = 0;
}

__global__ void k_count(const int* __restrict__ dst, int* __restrict__ cnt, int E) {
    int e = blockIdx.x * blockDim.x + threadIdx.x;
    if (e < E) atomicAdd(&cnt[dst[e]], 1);
}

// Single-block exclusive scan over N counts -> row (and cursor copy).
__global__ void k_scan(const int* __restrict__ cnt, int* __restrict__ row,
                       int* __restrict__ cur, int N) {
    __shared__ int sh[1024];
    __shared__ int s_carry;
    int tid = threadIdx.x;
    if (tid == 0) s_carry = 0;
    __syncthreads();
    for (int base = 0; base < N; base += 1024) {
        int i = base + tid;
        int v = (i < N) ? cnt[i] : 0;
        sh[tid] = v;
        __syncthreads();
        for (int off = 1; off < 1024; off <<= 1) {
            int t = (tid >= off) ? sh[tid - off] : 0;
            __syncthreads();
            sh[tid] += t;
            __syncthreads();
        }
        int excl = sh[tid] - v + s_carry;
        if (i < N) { row[i] = excl; cur[i] = excl; }
        __syncthreads();
        if (tid == 1023) s_carry += sh[1023];
        __syncthreads();
    }
    if (tid == 0) row[N] = s_carry;
}

__global__ void k_scatter(const int* __restrict__ src, const int* __restrict__ dst,
                          int* __restrict__ cur, int* __restrict__ col, int E) {
    int e = blockIdx.x * blockDim.x + threadIdx.x;
    if (e >= E) return;
    int slot = atomicAdd(&cur[dst[e]], 1);
    col[slot] = src[e];
}

// ---------------------------------------------------------------------------
// GEMM: out[N,O] = A[N,K] @ W[K,O] (+bias). blockDim.x == O.
// ---------------------------------------------------------------------------
__global__ void k_gemm(const float* __restrict__ A, const float* __restrict__ W,
                       const float* __restrict__ bias,
                       float* __restrict__ out, int N, int K, int O) {
    __shared__ float Ws[32][128];
    __shared__ float Hs[32][33];
    int tid  = threadIdx.x;
    int row0 = blockIdx.x * 32;

    float acc[32];
#pragma unroll
    for (int r = 0; r < 32; r++) acc[r] = 0.f;

    for (int kt = 0; kt < K; kt += 32) {
#pragma unroll
        for (int k = 0; k < 32; k++) Ws[k][tid] = W[(kt + k) * O + tid];
        for (int i = tid; i < 32 * 32; i += O) {
            int r = i >> 5, c = i & 31;
            int row = row0 + r;
            Hs[r][c] = (row < N) ? A[row * K + kt + c] : 0.f;
        }
        __syncthreads();
#pragma unroll 4
        for (int c = 0; c < 32; c++) {
            float w = Ws[c][tid];
#pragma unroll
            for (int r = 0; r < 32; r++) acc[r] += Hs[r][c] * w;
        }
        __syncthreads();
    }

    float b = bias ? bias[tid] : 0.f;
    for (int r = 0; r < 32; r++) {
        int row = row0 + r;
        if (row < N) out[row * O + tid] = acc[r] + b;
    }
}

// ---------------------------------------------------------------------------
// Attention scores (warp per node)
// ---------------------------------------------------------------------------
__global__ void k_scores(const float* __restrict__ fh, const float* __restrict__ al,
                         const float* __restrict__ ar, float* __restrict__ el,
                         float* __restrict__ er, int N, int H) {
    int gt = blockIdx.x * blockDim.x + threadIdx.x;
    int n = gt >> 5, lane = gt & 31;
    if (n >= N) return;
    for (int h = 0; h < H; h++) {
        float2 v = *(const float2*)&fh[(n * H + h) * 64 + lane * 2];
        float2 a = *(const float2*)&al[h * 64 + lane * 2];
        float2 b = *(const float2*)&ar[h * 64 + lane * 2];
        float sl = v.x * a.x + v.y * a.y;
        float sr = v.x * b.x + v.y * b.y;
#pragma unroll
        for (int o = 16; o > 0; o >>= 1) {
            sl += __shfl_xor_sync(0xffffffffu, sl, o);
            sr += __shfl_xor_sync(0xffffffffu, sr, o);
        }
        if (lane == 0) { el[n * H + h] = sl; er[n * H + h] = sr; }
    }
}

// ---------------------------------------------------------------------------
// Fused per-dst aggregation: online edge-softmax + weighted sum + bias +
// residual + optional ELU. One warp per destination node; lane owns O/32
// consecutive output floats. H heads folded across the warp (O = H*64).
// ---------------------------------------------------------------------------
template <int O, int H, bool ELU>
__global__ void k_aggr(const int* __restrict__ row, const int* __restrict__ col,
                       const float* __restrict__ el, const float* __restrict__ er,
                       const float* __restrict__ fh, const float* __restrict__ bias,
                       const float* __restrict__ res, float* __restrict__ out, int N) {
    constexpr int VPT = O / 32;                 // floats per lane (4 or 2)
    int w    = (blockIdx.x * blockDim.x + threadIdx.x) >> 5;
    int lane = threadIdx.x & 31;
    if (w >= N) return;
    const int h = (lane * VPT) >> 6;            // head for this lane's slice

    const float er_t = er[w * H + h];
    const int e0 = row[w], e1 = row[w + 1];

    float m = -CUDART_INF_F, den = 0.f;
    float acc[VPT];
#pragma unroll
    for (int i = 0; i < VPT; i++) acc[i] = 0.f;

    for (int base = e0; base < e1; base += 32) {
        int myidx = base + lane;
        int s_l = (myidx < e1) ? col[myidx] : 0;
        int n = min(32, e1 - base);
        for (int j = 0; j < n; j++) {
            int s = __shfl_sync(0xffffffffu, s_l, j);
            float z = el[s * H + h] + er_t;
            z = z > 0.f ? z : 0.2f * z;
            float nm = fmaxf(m, z);
            float sc = __expf(m - nm);          // first iter: exp(-inf)=0
            float p  = __expf(z - nm);
            m = nm;
            den = den * sc + p;
            if (VPT == 4) {
                float4 f = *(const float4*)&fh[s * O + lane * 4];
                acc[0] = acc[0] * sc + p * f.x;
                acc[1] = acc[1] * sc + p * f.y;
                acc[2] = acc[2] * sc + p * f.z;
                acc[3] = acc[3] * sc + p * f.w;
            } else {
                float2 f = *(const float2*)&fh[s * O + lane * 2];
                acc[0] = acc[0] * sc + p * f.x;
                acc[1] = acc[1] * sc + p * f.y;
            }
        }
    }

    float inv = 1.f / fmaxf(den, 1e-9f);
#pragma unroll
    for (int i = 0; i < VPT; i++) {
        int c = lane * VPT + i;
        float v = acc[i] * inv + bias[c];
        if (res) v += res[w * O + c];
        if (ELU) v = v > 0.f ? v : (__expf(v) - 1.f);
        out[w * O + c] = v;
    }
}

// ---------------------------------------------------------------------------
// Launch
// ---------------------------------------------------------------------------
extern "C" void kernel_launch(void* const* d_in, const int* in_sizes, int n_in,
                              void* d_out, int out_size) {
    const int*   feats = (const int*)  d_in[0];
    const float* fv    = (const float*)d_in[1];
    const int*   src   = (const int*)  d_in[2];
    const int*   dst   = (const int*)  d_in[3];
    const float* emb   = (const float*)d_in[4];
    const float* W0    = (const float*)d_in[5];
    const float* al0   = (const float*)d_in[6];
    const float* ar0   = (const float*)d_in[7];
    const float* b0    = (const float*)d_in[8];
    const float* W1    = (const float*)d_in[9];
    const float* al1   = (const float*)d_in[10];
    const float* ar1   = (const float*)d_in[11];
    const float* b1    = (const float*)d_in[12];
    const float* W2    = (const float*)d_in[13];
    const float* al2   = (const float*)d_in[14];
    const float* ar2   = (const float*)d_in[15];
    const float* b2    = (const float*)d_in[16];
    const float* resW2 = (const float*)d_in[17];
    float* out = (float*)d_out;

    const int N = in_sizes[0] / 8;
    const int E = in_sizes[2];

    float *hA, *hB, *fh, *el, *er;
    int *row, *cur, *col;
    cudaGetSymbolAddress((void**)&hA,  g_hA);
    cudaGetSymbolAddress((void**)&hB,  g_hB);
    cudaGetSymbolAddress((void**)&fh,  g_fh);
    cudaGetSymbolAddress((void**)&el,  g_el);
    cudaGetSymbolAddress((void**)&er,  g_er);
    cudaGetSymbolAddress((void**)&row, g_row);
    cudaGetSymbolAddress((void**)&cur, g_cur);
    cudaGetSymbolAddress((void**)&col, g_col);

    const int TB = 256;
    int gemmBlocks  = (N + 31) / 32;
    int scoreBlocks = (N * 32 + TB - 1) / TB;
    int aggrBlocks  = (N * 32 + TB - 1) / TB;

    // ---- CSR build (once; reused by all 3 layers) ----
    k_zero   <<<(N + TB - 1) / TB, TB>>>(cur, N);
    k_count  <<<(E + TB - 1) / TB, TB>>>(dst, cur, E);
    k_scan   <<<1, 1024>>>(cur, row, cur, N);
    k_scatter<<<(E + TB - 1) / TB, TB>>>(src, dst, cur, col, E);

    // ---- Embedding -> hA [N,64] ----
    k_embed<<<(N * 64 + TB - 1) / TB, TB>>>(feats, fv, emb, hA, N);

    // ---- Layer 0: K=64 -> H=2 (O=128), no residual, ELU, out -> hB ----
    k_gemm<<<gemmBlocks, 128>>>(hA, W0, nullptr, fh, N, 64, 128);
    k_scores<<<scoreBlocks, TB>>>(fh, al0, ar0, el, er, N, 2);
    k_aggr<128, 2, true><<<aggrBlocks, TB>>>(row, col, el, er, fh, b0, nullptr, hB, N);

    // ---- Layer 1: K=128 -> H=2 (O=128), identity residual, ELU, out -> hA ----
    k_gemm<<<gemmBlocks, 128>>>(hB, W1, nullptr, fh, N, 128, 128);
    k_scores<<<scoreBlocks, TB>>>(fh, al1, ar1, el, er, N, 2);
    k_aggr<128, 2, true><<<aggrBlocks, TB>>>(row, col, el, er, fh, b1, hB, hA, N);

    // ---- Layer 2: K=128 -> H=1 (O=64), projected residual, no act, out -> d_out ----
    k_gemm<<<gemmBlocks, 64>>>(hA, W2, nullptr, fh, N, 128, 64);
    k_scores<<<scoreBlocks, TB>>>(fh, al2, ar2, el, er, N, 1);
    k_gemm<<<gemmBlocks, 64>>>(hA, resW2, nullptr, hB, N, 128, 64);  // residual proj
    k_aggr<64, 1, false><<<aggrBlocks, TB>>>(row, col, el, er, fh, b2, hB, out, N);
}

// round 3
// speedup vs baseline: 1.9479x; 1.0589x over previous
#include <cuda_runtime.h>
#include <math_constants.h>

// ---------------------------------------------------------------------------
// 3-layer GAT, N=50000 nodes, E=800000 edges, D=64 per head.
// dst-CSR built once, fused softmax+aggregate per layer.
// R3: two-pass softmax (no rescale chain, MLP-4 accumulate banks),
//     float4-vectorized GEMM inner loop, shfl-based scan.
// ---------------------------------------------------------------------------

#define NMAX 50000
#define EMAX 800000

__device__ float g_hA[NMAX * 128];
__device__ float g_hB[NMAX * 128];
__device__ float g_fh[NMAX * 128];
__device__ float g_el[NMAX * 2];
__device__ float g_er[NMAX * 2];
__device__ int   g_row[NMAX + 1];
__device__ int   g_cur[NMAX];
__device__ int   g_col[EMAX];

__device__ __forceinline__ float lrelu(float v) { return v > 0.f ? v : 0.2f * v; }

// ---------------------------------------------------------------------------
__global__ void k_embed(const int* __restrict__ feats, const float* __restrict__ fv,
                        const float* __restrict__ emb, float* __restrict__ h, int N) {
    int i = blockIdx.x * blockDim.x + threadIdx.x;
    if (i >= N * 64) return;
    int n = i >> 6, d = i & 63;
    h[i] = emb[(long long)feats[n] * 64 + d] * fv[n];
}

// ---------------------------------------------------------------------------
// CSR build
// ---------------------------------------------------------------------------
__global__ void k_zero(int* __restrict__ c, int n) {
    int i = blockIdx.x * blockDim.x + threadIdx.x;
    if (i < n) c[i] = 0;
}

__global__ void k_count(const int* __restrict__ dst, int* __restrict__ cnt, int E) {
    int e = blockIdx.x * blockDim.x + threadIdx.x;
    if (e < E) atomicAdd(&cnt[dst[e]], 1);
}

// Single-block exclusive scan (shfl-based), 1024 threads.
__global__ void k_scan(const int* __restrict__ cnt, int* __restrict__ row,
                       int* __restrict__ cur, int N) {
    __shared__ int wsum[32];
    int tid = threadIdx.x, lane = tid & 31, wid = tid >> 5;
    int carry = 0;
    for (int base = 0; base < N; base += 1024) {
        int i = base + tid;
        int v = (i < N) ? cnt[i] : 0;
        int x = v;
#pragma unroll
        for (int off = 1; off < 32; off <<= 1) {
            int t = __shfl_up_sync(0xffffffffu, x, off);
            if (lane >= off) x += t;
        }
        if (lane == 31) wsum[wid] = x;
        __syncthreads();
        if (wid == 0) {
            int y = wsum[lane];
#pragma unroll
            for (int off = 1; off < 32; off <<= 1) {
                int t = __shfl_up_sync(0xffffffffu, y, off);
                if (lane >= off) y += t;
            }
            wsum[lane] = y;
        }
        __syncthreads();
        int warpoff = (wid == 0) ? 0 : wsum[wid - 1];
        int total = wsum[31];
        int excl = carry + warpoff + x - v;
        if (i < N) { row[i] = excl; cur[i] = excl; }
        carry += total;
        __syncthreads();
    }
    if (tid == 0) row[N] = carry;
}

__global__ void k_scatter(const int* __restrict__ src, const int* __restrict__ dst,
                          int* __restrict__ cur, int* __restrict__ col, int E) {
    int e = blockIdx.x * blockDim.x + threadIdx.x;
    if (e >= E) return;
    int slot = atomicAdd(&cur[dst[e]], 1);
    col[slot] = src[e];
}

// ---------------------------------------------------------------------------
// GEMM: out[N,O] = A[N,K] @ W[K,O] (+bias). blockDim.x == O (64/128).
// float4 Hs reads (row stride 36 floats keeps 16B alignment).
// ---------------------------------------------------------------------------
__global__ void k_gemm(const float* __restrict__ A, const float* __restrict__ W,
                       const float* __restrict__ bias,
                       float* __restrict__ out, int N, int K, int O) {
    __shared__ float Ws[32][128];
    __shared__ float Hs[32 * 36];
    int tid  = threadIdx.x;
    int row0 = blockIdx.x * 32;

    float acc[32];
#pragma unroll
    for (int r = 0; r < 32; r++) acc[r] = 0.f;

    for (int kt = 0; kt < K; kt += 32) {
#pragma unroll
        for (int k = 0; k < 32; k++) Ws[k][tid] = W[(kt + k) * O + tid];
        for (int i = tid; i < 32 * 32; i += O) {
            int r = i >> 5, c = i & 31;
            int rr = row0 + r;
            Hs[r * 36 + c] = (rr < N) ? A[rr * K + kt + c] : 0.f;
        }
        __syncthreads();
#pragma unroll
        for (int cg = 0; cg < 8; cg++) {
            float w0 = Ws[cg * 4 + 0][tid];
            float w1 = Ws[cg * 4 + 1][tid];
            float w2 = Ws[cg * 4 + 2][tid];
            float w3 = Ws[cg * 4 + 3][tid];
#pragma unroll
            for (int r = 0; r < 32; r++) {
                const float4 h = *(const float4*)&Hs[r * 36 + cg * 4];
                acc[r] += h.x * w0 + h.y * w1 + h.z * w2 + h.w * w3;
            }
        }
        __syncthreads();
    }

    float b = bias ? bias[tid] : 0.f;
#pragma unroll
    for (int r = 0; r < 32; r++) {
        int rr = row0 + r;
        if (rr < N) out[rr * O + tid] = acc[r] + b;
    }
}

// ---------------------------------------------------------------------------
// Attention scores (warp per node)
// ---------------------------------------------------------------------------
__global__ void k_scores(const float* __restrict__ fh, const float* __restrict__ al,
                         const float* __restrict__ ar, float* __restrict__ el,
                         float* __restrict__ er, int N, int H) {
    int gt = blockIdx.x * blockDim.x + threadIdx.x;
    int n = gt >> 5, lane = gt & 31;
    if (n >= N) return;
    for (int h = 0; h < H; h++) {
        float2 v = *(const float2*)&fh[(n * H + h) * 64 + lane * 2];
        float2 a = *(const float2*)&al[h * 64 + lane * 2];
        float2 b = *(const float2*)&ar[h * 64 + lane * 2];
        float sl = v.x * a.x + v.y * a.y;
        float sr = v.x * b.x + v.y * b.y;
#pragma unroll
        for (int o = 16; o > 0; o >>= 1) {
            sl += __shfl_xor_sync(0xffffffffu, sl, o);
            sr += __shfl_xor_sync(0xffffffffu, sr, o);
        }
        if (lane == 0) { el[n * H + h] = sl; er[n * H + h] = sr; }
    }
}

// ---------------------------------------------------------------------------
// Fused per-dst aggregation, two-pass softmax:
//   pass 1: lane-parallel max over incoming edges (warp-reduced)
//   pass 2: lane-parallel p=exp(z-m) + den, broadcast p via shfl,
//           accumulate fh rows into 4 independent banks (MLP 4).
// One warp per node; lane owns O/32 consecutive output floats.
// ---------------------------------------------------------------------------
template <int O, int H, bool ELU>
__global__ void __launch_bounds__(256)
k_aggr(const int* __restrict__ row, const int* __restrict__ col,
       const float* __restrict__ el, const float* __restrict__ er,
       const float* __restrict__ fh, const float* __restrict__ bias,
       const float* __restrict__ res, float* __restrict__ out, int N) {
    constexpr int VPT = O / 32;                 // 4 (H=2) or 2 (H=1)
    const unsigned FULL = 0xffffffffu;
    int w    = (blockIdx.x * blockDim.x + threadIdx.x) >> 5;
    int lane = threadIdx.x & 31;
    if (w >= N) return;
    const bool topHalf = (H == 2) && ((lane * VPT) >= 64);

    const float er0 = er[w * H + 0];
    const float er1 = (H == 2) ? er[w * H + 1] : 0.f;
    const int e0 = row[w], e1 = row[w + 1];

    // ---- pass 1: max ----
    float m0 = -CUDART_INF_F, m1 = -CUDART_INF_F;
    for (int i = e0 + lane; i < e1; i += 32) {
        int s = col[i];
        if (H == 2) {
            float2 ev = *(const float2*)&el[s * 2];
            m0 = fmaxf(m0, lrelu(ev.x + er0));
            m1 = fmaxf(m1, lrelu(ev.y + er1));
        } else {
            m0 = fmaxf(m0, lrelu(el[s] + er0));
        }
    }
#pragma unroll
    for (int o = 16; o > 0; o >>= 1) {
        m0 = fmaxf(m0, __shfl_xor_sync(FULL, m0, o));
        if (H == 2) m1 = fmaxf(m1, __shfl_xor_sync(FULL, m1, o));
    }

    // ---- pass 2: p, den, accumulate ----
    float den0 = 0.f, den1 = 0.f;
    float acc[4][VPT];
#pragma unroll
    for (int k = 0; k < 4; k++)
#pragma unroll
        for (int i = 0; i < VPT; i++) acc[k][i] = 0.f;

    for (int base = e0; base < e1; base += 32) {
        int idx = base + lane;
        bool valid = idx < e1;
        int s_l = valid ? col[idx] : 0;
        float p0_l = 0.f, p1_l = 0.f;
        if (valid) {
            if (H == 2) {
                float2 ev = *(const float2*)&el[s_l * 2];
                p0_l = __expf(lrelu(ev.x + er0) - m0);
                p1_l = __expf(lrelu(ev.y + er1) - m1);
                den0 += p0_l; den1 += p1_l;
            } else {
                p0_l = __expf(lrelu(el[s_l] + er0) - m0);
                den0 += p0_l;
            }
        }
        int n = min(32, e1 - base);
        int j = 0;
        for (; j + 3 < n; j += 4) {
#pragma unroll
            for (int k = 0; k < 4; k++) {
                int   s  = __shfl_sync(FULL, s_l,  j + k);
                float pa = __shfl_sync(FULL, p0_l, j + k);
                float p;
                if (H == 2) {
                    float pb = __shfl_sync(FULL, p1_l, j + k);
                    p = topHalf ? pb : pa;
                } else p = pa;
                if (VPT == 4) {
                    const float4 f = *(const float4*)&fh[(size_t)s * O + lane * 4];
                    acc[k][0] += p * f.x; acc[k][1] += p * f.y;
                    acc[k][2] += p * f.z; acc[k][3] += p * f.w;
                } else {
                    const float2 f = *(const float2*)&fh[(size_t)s * O + lane * 2];
                    acc[k][0] += p * f.x; acc[k][1] += p * f.y;
                }
            }
        }
        for (; j < n; j++) {
            int   s  = __shfl_sync(FULL, s_l,  j);
            float pa = __shfl_sync(FULL, p0_l, j);
            float p;
            if (H == 2) {
                float pb = __shfl_sync(FULL, p1_l, j);
                p = topHalf ? pb : pa;
            } else p = pa;
            if (VPT == 4) {
                const float4 f = *(const float4*)&fh[(size_t)s * O + lane * 4];
                acc[0][0] += p * f.x; acc[0][1] += p * f.y;
                acc[0][2] += p * f.z; acc[0][3] += p * f.w;
            } else {
                const float2 f = *(const float2*)&fh[(size_t)s * O + lane * 2];
                acc[0][0] += p * f.x; acc[0][1] += p * f.y;
            }
        }
    }

#pragma unroll
    for (int o = 16; o > 0; o >>= 1) {
        den0 += __shfl_xor_sync(FULL, den0, o);
        if (H == 2) den1 += __shfl_xor_sync(FULL, den1, o);
    }
    float den = (H == 2 && topHalf) ? den1 : den0;
    float inv = 1.f / fmaxf(den, 1e-9f);

#pragma unroll
    for (int i = 0; i < VPT; i++) {
        int c = lane * VPT + i;
        float v = (acc[0][i] + acc[1][i] + acc[2][i] + acc[3][i]) * inv + bias[c];
        if (res) v += res[w * O + c];
        if (ELU) v = v > 0.f ? v : (__expf(v) - 1.f);
        out[w * O + c] = v;
    }
}

// ---------------------------------------------------------------------------
extern "C" void kernel_launch(void* const* d_in, const int* in_sizes, int n_in,
                              void* d_out, int out_size) {
    const int*   feats = (const int*)  d_in[0];
    const float* fv    = (const float*)d_in[1];
    const int*   src   = (const int*)  d_in[2];
    const int*   dst   = (const int*)  d_in[3];
    const float* emb   = (const float*)d_in[4];
    const float* W0    = (const float*)d_in[5];
    const float* al0   = (const float*)d_in[6];
    const float* ar0   = (const float*)d_in[7];
    const float* b0    = (const float*)d_in[8];
    const float* W1    = (const float*)d_in[9];
    const float* al1   = (const float*)d_in[10];
    const float* ar1   = (const float*)d_in[11];
    const float* b1    = (const float*)d_in[12];
    const float* W2    = (const float*)d_in[13];
    const float* al2   = (const float*)d_in[14];
    const float* ar2   = (const float*)d_in[15];
    const float* b2    = (const float*)d_in[16];
    const float* resW2 = (const float*)d_in[17];
    float* out = (float*)d_out;

    const int N = in_sizes[0] / 8;
    const int E = in_sizes[2];

    float *hA, *hB, *fh, *el, *er;
    int *row, *cur, *col;
    cudaGetSymbolAddress((void**)&hA,  g_hA);
    cudaGetSymbolAddress((void**)&hB,  g_hB);
    cudaGetSymbolAddress((void**)&fh,  g_fh);
    cudaGetSymbolAddress((void**)&el,  g_el);
    cudaGetSymbolAddress((void**)&er,  g_er);
    cudaGetSymbolAddress((void**)&row, g_row);
    cudaGetSymbolAddress((void**)&cur, g_cur);
    cudaGetSymbolAddress((void**)&col, g_col);

    const int TB = 256;
    int gemmBlocks  = (N + 31) / 32;
    int scoreBlocks = (N * 32 + TB - 1) / TB;
    int aggrBlocks  = (N * 32 + TB - 1) / TB;

    // CSR build (reused by all layers)
    k_zero   <<<(N + TB - 1) / TB, TB>>>(cur, N);
    k_count  <<<(E + TB - 1) / TB, TB>>>(dst, cur, E);
    k_scan   <<<1, 1024>>>(cur, row, cur, N);
    k_scatter<<<(E + TB - 1) / TB, TB>>>(src, dst, cur, col, E);

    k_embed<<<(N * 64 + TB - 1) / TB, TB>>>(feats, fv, emb, hA, N);

    // Layer 0: K=64 -> H=2 (O=128), no residual, ELU, -> hB
    k_gemm<<<gemmBlocks, 128>>>(hA, W0, nullptr, fh, N, 64, 128);
    k_scores<<<scoreBlocks, TB>>>(fh, al0, ar0, el, er, N, 2);
    k_aggr<128, 2, true><<<aggrBlocks, TB>>>(row, col, el, er, fh, b0, nullptr, hB, N);

    // Layer 1: K=128 -> H=2 (O=128), identity residual, ELU, -> hA
    k_gemm<<<gemmBlocks, 128>>>(hB, W1, nullptr, fh, N, 128, 128);
    k_scores<<<scoreBlocks, TB>>>(fh, al1, ar1, el, er, N, 2);
    k_aggr<128, 2, true><<<aggrBlocks, TB>>>(row, col, el, er, fh, b1, hB, hA, N);

    // Layer 2: K=128 -> H=1 (O=64), projected residual, no act, -> d_out
    k_gemm<<<gemmBlocks, 64>>>(hA, W2, nullptr, fh, N, 128, 64);
    k_scores<<<scoreBlocks, TB>>>(fh, al2, ar2, el, er, N, 1);
    k_gemm<<<gemmBlocks, 64>>>(hA, resW2, nullptr, hB, N, 128, 64);
    k_aggr<64, 1, false><<<aggrBlocks, TB>>>(row, col, el, er, fh, b2, hB, out, N);
}

// round 4
// speedup vs baseline: 2.2556x; 1.1580x over previous
#include <cuda_runtime.h>
#include <math_constants.h>

// ---------------------------------------------------------------------------
// 3-layer GAT, N=50000 nodes, E=800000 edges, D=64 per head.
// R4: packed f32x2 GEMM (FFMA2), scores fused into GEMM epilogue,
//     single-pass softmax aggregation, layer-2 GEMMs merged via [W2|resW2].
// ---------------------------------------------------------------------------

#define NMAX 50000
#define EMAX 800000

__device__ float g_hA[NMAX * 128];
__device__ float g_hB[NMAX * 128];
__device__ float g_fh[NMAX * 128];
__device__ float g_el[NMAX * 2];
__device__ float g_er[NMAX * 2];
__device__ float g_Wc[128 * 128];
__device__ int   g_row[NMAX + 1];
__device__ int   g_cur[NMAX];
__device__ int   g_col[EMAX];

__device__ __forceinline__ float lrelu(float v) { return v > 0.f ? v : 0.2f * v; }

__device__ __forceinline__ unsigned long long pack2(float lo, float hi) {
    unsigned long long r;
    asm("mov.b64 %0, {%1, %2};" : "=l"(r) : "r"(__float_as_uint(lo)), "r"(__float_as_uint(hi)));
    return r;
}
__device__ __forceinline__ void unpack2(unsigned long long v, float& lo, float& hi) {
    unsigned a, b;
    asm("mov.b64 {%0, %1}, %2;" : "=r"(a), "=r"(b) : "l"(v));
    lo = __uint_as_float(a); hi = __uint_as_float(b);
}
__device__ __forceinline__ void fma2(unsigned long long& d, unsigned long long a,
                                     unsigned long long b) {
    asm("fma.rn.f32x2 %0, %1, %2, %0;" : "+l"(d) : "l"(a), "l"(b));
}

// ---------------------------------------------------------------------------
// Embedding: h[n,0:64] = emb[feats[n]] * fv[n]   (float4 vectorized)
// ---------------------------------------------------------------------------
__global__ void k_embed(const int* __restrict__ feats, const float* __restrict__ fv,
                        const float* __restrict__ emb, float* __restrict__ h, int N) {
    int i = blockIdx.x * blockDim.x + threadIdx.x;
    if (i >= N * 16) return;
    int n = i >> 4, d4 = i & 15;
    float s = fv[n];
    float4 e = *(const float4*)&emb[(long long)feats[n] * 64 + d4 * 4];
    e.x *= s; e.y *= s; e.z *= s; e.w *= s;
    *(float4*)&h[n * 64 + d4 * 4] = e;
}

// ---------------------------------------------------------------------------
// CSR build
// ---------------------------------------------------------------------------
__global__ void k_zero(int* __restrict__ c, int n) {
    int i = blockIdx.x * blockDim.x + threadIdx.x;
    if (i < n) c[i] = 0;
}
__global__ void k_count(const int* __restrict__ dst, int* __restrict__ cnt, int E) {
    int e = blockIdx.x * blockDim.x + threadIdx.x;
    if (e < E) atomicAdd(&cnt[dst[e]], 1);
}
__global__ void k_scan(const int* __restrict__ cnt, int* __restrict__ row,
                       int* __restrict__ cur, int N) {
    __shared__ int wsum[32];
    int tid = threadIdx.x, lane = tid & 31, wid = tid >> 5;
    int carry = 0;
    for (int base = 0; base < N; base += 1024) {
        int i = base + tid;
        int v = (i < N) ? cnt[i] : 0;
        int x = v;
#pragma unroll
        for (int off = 1; off < 32; off <<= 1) {
            int t = __shfl_up_sync(0xffffffffu, x, off);
            if (lane >= off) x += t;
        }
        if (lane == 31) wsum[wid] = x;
        __syncthreads();
        if (wid == 0) {
            int y = wsum[lane];
#pragma unroll
            for (int off = 1; off < 32; off <<= 1) {
                int t = __shfl_up_sync(0xffffffffu, y, off);
                if (lane >= off) y += t;
            }
            wsum[lane] = y;
        }
        __syncthreads();
        int warpoff = (wid == 0) ? 0 : wsum[wid - 1];
        int total = wsum[31];
        int excl = carry + warpoff + x - v;
        if (i < N) { row[i] = excl; cur[i] = excl; }
        carry += total;
        __syncthreads();
    }
    if (tid == 0) row[N] = carry;
}
__global__ void k_scatter(const int* __restrict__ src, const int* __restrict__ dst,
                          int* __restrict__ cur, int* __restrict__ col, int E) {
    int e = blockIdx.x * blockDim.x + threadIdx.x;
    if (e >= E) return;
    int slot = atomicAdd(&cur[dst[e]], 1);
    col[slot] = src[e];
}

// Wc = [W2 | resW2]  (both [128,64] -> [128,128])
__global__ void k_wcat(const float* __restrict__ W2, const float* __restrict__ resW2,
                       float* __restrict__ Wc) {
    int i = blockIdx.x * blockDim.x + threadIdx.x;
    if (i >= 128 * 128) return;
    int k = i >> 7, j = i & 127;
    Wc[i] = (j < 64) ? W2[k * 64 + j] : resW2[k * 64 + (j - 64)];
}

// ---------------------------------------------------------------------------
// Fused GEMM + scores. Block = 128 threads, 32 rows. out[N,128] = A @ W.
// Packed f32x2 accumulation over row pairs.
// HS = number of score heads (scores over cols [0, HS*64)).
// SPLIT: cols 0-63 -> out (stride 64), cols 64-127 -> out2 (stride 64).
// ---------------------------------------------------------------------------
template <int HS, bool SPLIT>
__global__ void __launch_bounds__(128)
k_gemm(const float* __restrict__ A, const float* __restrict__ W,
       float* __restrict__ out, float* __restrict__ out2,
       const float* __restrict__ al, const float* __restrict__ ar,
       float* __restrict__ el, float* __restrict__ er, int N, int K) {
    __shared__ float Ws[32][128];
    __shared__ float Hs[32][34];      // [c][r], row pairs at even r
    __shared__ float S[32][132];      // output staging for scores
    int tid  = threadIdx.x;
    int row0 = blockIdx.x * 32;

    unsigned long long acc2[16];
#pragma unroll
    for (int i = 0; i < 16; i++) acc2[i] = 0ull;

    for (int kt = 0; kt < K; kt += 32) {
#pragma unroll
        for (int k = 0; k < 32; k++) Ws[k][tid] = W[(kt + k) * 128 + tid];
#pragma unroll
        for (int i = tid; i < 32 * 32; i += 128) {
            int r = i >> 5, c = i & 31;
            int rr = row0 + r;
            Hs[c][r] = (rr < N) ? A[rr * K + kt + c] : 0.f;
        }
        __syncthreads();
#pragma unroll
        for (int c = 0; c < 32; c++) {
            float w = Ws[c][tid];
            unsigned long long w2 = pack2(w, w);
#pragma unroll
            for (int r2 = 0; r2 < 16; r2++) {
                unsigned long long h = *(const unsigned long long*)&Hs[c][2 * r2];
                fma2(acc2[r2], h, w2);
            }
        }
        __syncthreads();
    }

    // epilogue: unpack, store to global + shared staging
#pragma unroll
    for (int r2 = 0; r2 < 16; r2++) {
        float lo, hi;
        unpack2(acc2[r2], lo, hi);
        int ra = 2 * r2, rb = 2 * r2 + 1;
        S[ra][tid] = lo;
        S[rb][tid] = hi;
        int rra = row0 + ra, rrb = row0 + rb;
        if (SPLIT) {
            if (tid < 64) {
                if (rra < N) out[rra * 64 + tid] = lo;
                if (rrb < N) out[rrb * 64 + tid] = hi;
            } else {
                if (rra < N) out2[rra * 64 + tid - 64] = lo;
                if (rrb < N) out2[rrb * 64 + tid - 64] = hi;
            }
        } else {
            if (rra < N) out[rra * 128 + tid] = lo;
            if (rrb < N) out[rrb * 128 + tid] = hi;
        }
    }
    __syncthreads();

    // scores: warp w handles rows 8w..8w+7; lane owns 4 cols (lane*4).
    int wid = tid >> 5, lane = tid & 31;
    float4 a4 = make_float4(0.f, 0.f, 0.f, 0.f);
    float4 r4 = make_float4(0.f, 0.f, 0.f, 0.f);
    if (lane * 4 < HS * 64) {
        a4 = *(const float4*)&al[lane * 4];
        r4 = *(const float4*)&ar[lane * 4];
    }
#pragma unroll
    for (int q = 0; q < 8; q++) {
        int r = wid * 8 + q;
        int rr = row0 + r;
        float4 f = *(const float4*)&S[r][lane * 4];
        float sl = f.x * a4.x + f.y * a4.y + f.z * a4.z + f.w * a4.w;
        float sr = f.x * r4.x + f.y * r4.y + f.z * r4.z + f.w * r4.w;
#pragma unroll
        for (int off = 8; off > 0; off >>= 1) {
            sl += __shfl_xor_sync(0xffffffffu, sl, off);
            sr += __shfl_xor_sync(0xffffffffu, sr, off);
        }
        int h = lane >> 4;   // 16-lane group id (head)
        if ((lane & 15) == 0 && h < HS && rr < N) {
            el[rr * HS + h] = sl;
            er[rr * HS + h] = sr;
        }
    }
}

// ---------------------------------------------------------------------------
// Fused aggregation: single-pass softmax (no max; scores are O(1), exp safe),
// 4-bank MLP accumulation. One warp per dst node.
// ---------------------------------------------------------------------------
template <int O, int H, bool ELU>
__global__ void __launch_bounds__(256)
k_aggr(const int* __restrict__ row, const int* __restrict__ col,
       const float* __restrict__ el, const float* __restrict__ er,
       const float* __restrict__ fh, const float* __restrict__ bias,
       const float* __restrict__ res, float* __restrict__ out, int N) {
    constexpr int VPT = O / 32;                 // 4 (H=2) or 2 (H=1)
    const unsigned FULL = 0xffffffffu;
    int w    = (blockIdx.x * blockDim.x + threadIdx.x) >> 5;
    int lane = threadIdx.x & 31;
    if (w >= N) return;
    const bool topHalf = (H == 2) && ((lane * VPT) >= 64);

    const float er0 = er[w * H + 0];
    const float er1 = (H == 2) ? er[w * H + 1] : 0.f;
    const int e0 = row[w], e1 = row[w + 1];

    float den0 = 0.f, den1 = 0.f;
    float acc[4][VPT];
#pragma unroll
    for (int k = 0; k < 4; k++)
#pragma unroll
        for (int i = 0; i < VPT; i++) acc[k][i] = 0.f;

    for (int base = e0; base < e1; base += 32) {
        int idx = base + lane;
        bool valid = idx < e1;
        int s_l = valid ? col[idx] : 0;
        float p0_l = 0.f, p1_l = 0.f;
        if (valid) {
            if (H == 2) {
                float2 ev = *(const float2*)&el[s_l * 2];
                p0_l = __expf(lrelu(ev.x + er0));
                p1_l = __expf(lrelu(ev.y + er1));
                den0 += p0_l; den1 += p1_l;
            } else {
                p0_l = __expf(lrelu(el[s_l] + er0));
                den0 += p0_l;
            }
        }
        int n = min(32, e1 - base);
        int j = 0;
        for (; j + 3 < n; j += 4) {
#pragma unroll
            for (int k = 0; k < 4; k++) {
                int   s  = __shfl_sync(FULL, s_l,  j + k);
                float pa = __shfl_sync(FULL, p0_l, j + k);
                float p;
                if (H == 2) {
                    float pb = __shfl_sync(FULL, p1_l, j + k);
                    p = topHalf ? pb : pa;
                } else p = pa;
                if (VPT == 4) {
                    const float4 f = *(const float4*)&fh[(size_t)s * O + lane * 4];
                    acc[k][0] += p * f.x; acc[k][1] += p * f.y;
                    acc[k][2] += p * f.z; acc[k][3] += p * f.w;
                } else {
                    const float2 f = *(const float2*)&fh[(size_t)s * O + lane * 2];
                    acc[k][0] += p * f.x; acc[k][1] += p * f.y;
                }
            }
        }
        for (; j < n; j++) {
            int   s  = __shfl_sync(FULL, s_l,  j);
            float pa = __shfl_sync(FULL, p0_l, j);
            float p;
            if (H == 2) {
                float pb = __shfl_sync(FULL, p1_l, j);
                p = topHalf ? pb : pa;
            } else p = pa;
            if (VPT == 4) {
                const float4 f = *(const float4*)&fh[(size_t)s * O + lane * 4];
                acc[0][0] += p * f.x; acc[0][1] += p * f.y;
                acc[0][2] += p * f.z; acc[0][3] += p * f.w;
            } else {
                const float2 f = *(const float2*)&fh[(size_t)s * O + lane * 2];
                acc[0][0] += p * f.x; acc[0][1] += p * f.y;
            }
        }
    }

#pragma unroll
    for (int o = 16; o > 0; o >>= 1) {
        den0 += __shfl_xor_sync(FULL, den0, o);
        if (H == 2) den1 += __shfl_xor_sync(FULL, den1, o);
    }
    float den = (H == 2 && topHalf) ? den1 : den0;
    float inv = 1.f / fmaxf(den, 1e-9f);

#pragma unroll
    for (int i = 0; i < VPT; i++) {
        int c = lane * VPT + i;
        float v = (acc[0][i] + acc[1][i] + acc[2][i] + acc[3][i]) * inv + bias[c];
        if (res) v += res[w * O + c];
        if (ELU) v = v > 0.f ? v : (__expf(v) - 1.f);
        out[w * O + c] = v;
    }
}

// ---------------------------------------------------------------------------
extern "C" void kernel_launch(void* const* d_in, const int* in_sizes, int n_in,
                              void* d_out, int out_size) {
    const int*   feats = (const int*)  d_in[0];
    const float* fv    = (const float*)d_in[1];
    const int*   src   = (const int*)  d_in[2];
    const int*   dst   = (const int*)  d_in[3];
    const float* emb   = (const float*)d_in[4];
    const float* W0    = (const float*)d_in[5];
    const float* al0   = (const float*)d_in[6];
    const float* ar0   = (const float*)d_in[7];
    const float* b0    = (const float*)d_in[8];
    const float* W1    = (const float*)d_in[9];
    const float* al1   = (const float*)d_in[10];
    const float* ar1   = (const float*)d_in[11];
    const float* b1    = (const float*)d_in[12];
    const float* W2    = (const float*)d_in[13];
    const float* al2   = (const float*)d_in[14];
    const float* ar2   = (const float*)d_in[15];
    const float* b2    = (const float*)d_in[16];
    const float* resW2 = (const float*)d_in[17];
    float* out = (float*)d_out;

    const int N = in_sizes[0] / 8;
    const int E = in_sizes[2];

    float *hA, *hB, *fh, *el, *er, *Wc;
    int *row, *cur, *col;
    cudaGetSymbolAddress((void**)&hA,  g_hA);
    cudaGetSymbolAddress((void**)&hB,  g_hB);
    cudaGetSymbolAddress((void**)&fh,  g_fh);
    cudaGetSymbolAddress((void**)&el,  g_el);
    cudaGetSymbolAddress((void**)&er,  g_er);
    cudaGetSymbolAddress((void**)&Wc,  g_Wc);
    cudaGetSymbolAddress((void**)&row, g_row);
    cudaGetSymbolAddress((void**)&cur, g_cur);
    cudaGetSymbolAddress((void**)&col, g_col);

    const int TB = 256;
    int gemmBlocks = (N + 31) / 32;
    int aggrBlocks = (N * 32 + TB - 1) / TB;

    // CSR build (reused by all layers)
    k_zero   <<<(N + TB - 1) / TB, TB>>>(cur, N);
    k_count  <<<(E + TB - 1) / TB, TB>>>(dst, cur, E);
    k_scan   <<<1, 1024>>>(cur, row, cur, N);
    k_scatter<<<(E + TB - 1) / TB, TB>>>(src, dst, cur, col, E);

    k_wcat <<<(128 * 128 + TB - 1) / TB, TB>>>(W2, resW2, Wc);
    k_embed<<<(N * 16 + TB - 1) / TB, TB>>>(feats, fv, emb, hA, N);

    // Layer 0: K=64 -> H=2, no residual, ELU, -> hB
    k_gemm<2, false><<<gemmBlocks, 128>>>(hA, W0, fh, nullptr, al0, ar0, el, er, N, 64);
    k_aggr<128, 2, true><<<aggrBlocks, TB>>>(row, col, el, er, fh, b0, nullptr, hB, N);

    // Layer 1: K=128 -> H=2, identity residual, ELU, -> hA
    k_gemm<2, false><<<gemmBlocks, 128>>>(hB, W1, fh, nullptr, al1, ar1, el, er, N, 128);
    k_aggr<128, 2, true><<<aggrBlocks, TB>>>(row, col, el, er, fh, b1, hB, hA, N);

    // Layer 2: K=128, combined [W2|resW2]: fh (cols 0-63) + residual hB (cols 64-127)
    k_gemm<1, true><<<gemmBlocks, 128>>>(hA, Wc, fh, hB, al2, ar2, el, er, N, 128);
    k_aggr<64, 1, false><<<aggrBlocks, TB>>>(row, col, el, er, fh, b2, hB, out, N);
}

// round 6
// speedup vs baseline: 2.7813x; 1.2330x over previous
#include <cuda_runtime.h>
#include <cstdint>

// ---------------------------------------------------------------------------
// 3-layer GAT, N=50000 nodes, E=800000 edges.
// R6: mma.sync m16n8k8 TF32 GEMM (baseline PTX, works on compute_103),
//     fused score epilogue, multi-block CSR scan, merged layer-2 weights,
//     single-pass-softmax aggregation.
// ---------------------------------------------------------------------------

#define NMAX 50000
#define EMAX 800000

__device__ float g_hA[NMAX * 128];
__device__ float g_hB[NMAX * 128];
__device__ float g_fh[NMAX * 128];
__device__ float g_el[NMAX * 2];
__device__ float g_er[NMAX * 2];
__device__ float g_Wc[128 * 128];
__device__ int   g_row[NMAX + 1];
__device__ int   g_cur[NMAX];
__device__ int   g_col[EMAX];
__device__ int   g_bsum[64];

__device__ __forceinline__ float lrelu(float v) { return v > 0.f ? v : 0.2f * v; }

__device__ __forceinline__ uint32_t f2tf32(float f) {
    uint32_t r;
    asm("cvt.rna.tf32.f32 %0, %1;" : "=r"(r) : "f"(f));
    return r;
}

__device__ __forceinline__ void mma_tf32(float c[4], const uint32_t a[4],
                                         const uint32_t b[2]) {
    asm volatile(
        "mma.sync.aligned.m16n8k8.row.col.f32.tf32.tf32.f32 "
        "{%0,%1,%2,%3}, {%4,%5,%6,%7}, {%8,%9}, {%0,%1,%2,%3};"
        : "+f"(c[0]), "+f"(c[1]), "+f"(c[2]), "+f"(c[3])
        : "r"(a[0]), "r"(a[1]), "r"(a[2]), "r"(a[3]), "r"(b[0]), "r"(b[1]));
}

// ---------------------------------------------------------------------------
// Embedding
// ---------------------------------------------------------------------------
__global__ void k_embed(const int* __restrict__ feats, const float* __restrict__ fv,
                        const float* __restrict__ emb, float* __restrict__ h, int N) {
    int i = blockIdx.x * blockDim.x + threadIdx.x;
    if (i >= N * 16) return;
    int n = i >> 4, d4 = i & 15;
    float s = fv[n];
    float4 e = *(const float4*)&emb[(long long)feats[n] * 64 + d4 * 4];
    e.x *= s; e.y *= s; e.z *= s; e.w *= s;
    *(float4*)&h[n * 64 + d4 * 4] = e;
}

// ---------------------------------------------------------------------------
// CSR build (multi-block scan)
// ---------------------------------------------------------------------------
__global__ void k_zero(int* __restrict__ c, int n) {
    int i = blockIdx.x * blockDim.x + threadIdx.x;
    if (i < n) c[i] = 0;
}
__global__ void k_count(const int* __restrict__ dst, int* __restrict__ cnt, int E) {
    int e = blockIdx.x * blockDim.x + threadIdx.x;
    if (e < E) atomicAdd(&cnt[dst[e]], 1);
}
__global__ void k_bsum(const int* __restrict__ cnt, int* __restrict__ bsum, int N) {
    __shared__ int ws[32];
    int i = blockIdx.x * 1024 + threadIdx.x;
    int lane = threadIdx.x & 31, wid = threadIdx.x >> 5;
    int v = (i < N) ? cnt[i] : 0;
#pragma unroll
    for (int o = 16; o > 0; o >>= 1) v += __shfl_xor_sync(0xffffffffu, v, o);
    if (lane == 0) ws[wid] = v;
    __syncthreads();
    if (wid == 0) {
        int x = ws[lane];
#pragma unroll
        for (int o = 16; o > 0; o >>= 1) x += __shfl_xor_sync(0xffffffffu, x, o);
        if (lane == 0) bsum[blockIdx.x] = x;
    }
}
__global__ void k_bscan(int* __restrict__ bsum, int nb) {
    if (threadIdx.x == 0) {
        int s = 0;
        for (int i = 0; i < nb; i++) { int t = bsum[i]; bsum[i] = s; s += t; }
    }
}
__global__ void k_scan2(const int* __restrict__ cnt, const int* __restrict__ bsum,
                        int* __restrict__ row, int* __restrict__ cur, int N, int E) {
    __shared__ int ws[32];
    int i = blockIdx.x * 1024 + threadIdx.x;
    int lane = threadIdx.x & 31, wid = threadIdx.x >> 5;
    int v = (i < N) ? cnt[i] : 0;
    int x = v;
#pragma unroll
    for (int o = 1; o < 32; o <<= 1) {
        int t = __shfl_up_sync(0xffffffffu, x, o);
        if (lane >= o) x += t;
    }
    if (lane == 31) ws[wid] = x;
    __syncthreads();
    if (wid == 0) {
        int y = ws[lane];
#pragma unroll
        for (int o = 1; o < 32; o <<= 1) {
            int t = __shfl_up_sync(0xffffffffu, y, o);
            if (lane >= o) y += t;
        }
        ws[lane] = y;
    }
    __syncthreads();
    int excl = bsum[blockIdx.x] + (wid ? ws[wid - 1] : 0) + x - v;
    if (i < N) { row[i] = excl; cur[i] = excl; }
    if (i == 0) row[N] = E;
}
__global__ void k_scatter(const int* __restrict__ src, const int* __restrict__ dst,
                          int* __restrict__ cur, int* __restrict__ col, int E) {
    int e = blockIdx.x * blockDim.x + threadIdx.x;
    if (e >= E) return;
    int slot = atomicAdd(&cur[dst[e]], 1);
    col[slot] = src[e];
}

// Wc = [W2 | resW2]  ([128,64]+[128,64] -> [128,128] fp32)
__global__ void k_wcat(const float* __restrict__ W2, const float* __restrict__ resW2,
                       float* __restrict__ Wc) {
    int i = blockIdx.x * blockDim.x + threadIdx.x;
    if (i >= 128 * 128) return;
    int k = i >> 7, j = i & 127;
    Wc[i] = (j < 64) ? W2[k * 64 + j] : resW2[k * 64 + (j - 64)];
}

// ---------------------------------------------------------------------------
// TF32 mma.sync GEMM + fused scores. Block: 256 thr (8 warps), 64 rows x 128
// cols per block; each warp 32x32 (2 m-frags x 4 n-frags of m16n8k8).
// Dynamic smem: [stage 64*132 f][sW K*132 u32][sA 64*(K+4) u32].
// SPLIT: cols 0-63 -> out (stride 64), 64-127 -> out2 (stride 64).
// ---------------------------------------------------------------------------
template <int K, int HS, bool SPLIT>
__global__ void __launch_bounds__(256)
k_mgemm(const float* __restrict__ A, const float* __restrict__ W,
        float* __restrict__ out, float* __restrict__ out2,
        const float* __restrict__ al, const float* __restrict__ ar,
        float* __restrict__ el, float* __restrict__ er, int N) {
    extern __shared__ char smraw[];
    float*    stage = (float*)smraw;                       // 64*132
    uint32_t* sW    = (uint32_t*)(smraw + 64 * 132 * 4);   // K*132
    uint32_t* sA    = (uint32_t*)(smraw + 64 * 132 * 4 + K * 132 * 4); // 64*(K+4)
    constexpr int SAS = K + 4;

    const int tid = threadIdx.x;
    const int wid = tid >> 5, lane = tid & 31;
    const int g = lane >> 2, t = lane & 3;
    const int row0 = blockIdx.x * 64;
    const int wRow = (wid >> 2) * 32, wCol = (wid & 3) * 32;

    // load W -> sW (tf32)
    for (int i = tid; i < K * 32; i += 256) {
        int k = i >> 5, c4 = i & 31;
        float4 v = *(const float4*)&W[k * 128 + c4 * 4];
        uint4 u;
        u.x = f2tf32(v.x); u.y = f2tf32(v.y); u.z = f2tf32(v.z); u.w = f2tf32(v.w);
        *(uint4*)&sW[k * 132 + c4 * 4] = u;
    }
    // load A tile -> sA (tf32)
    constexpr int C4 = K / 4;
    for (int i = tid; i < 64 * C4; i += 256) {
        int r = i / C4, c4 = i % C4, rr = row0 + r;
        float4 v = make_float4(0.f, 0.f, 0.f, 0.f);
        if (rr < N) v = *(const float4*)&A[(size_t)rr * K + c4 * 4];
        uint4 u;
        u.x = f2tf32(v.x); u.y = f2tf32(v.y); u.z = f2tf32(v.z); u.w = f2tf32(v.w);
        *(uint4*)&sA[r * SAS + c4 * 4] = u;
    }
    __syncthreads();

    float c[2][4][4];
#pragma unroll
    for (int mf = 0; mf < 2; mf++)
#pragma unroll
        for (int nf = 0; nf < 4; nf++)
#pragma unroll
            for (int i = 0; i < 4; i++) c[mf][nf][i] = 0.f;

#pragma unroll
    for (int ks = 0; ks < K / 8; ks++) {
        const int k0 = ks * 8;
        uint32_t a[2][4];
#pragma unroll
        for (int mf = 0; mf < 2; mf++) {
            int rb = wRow + mf * 16;
            a[mf][0] = sA[(rb + g)     * SAS + k0 + t];
            a[mf][1] = sA[(rb + g + 8) * SAS + k0 + t];
            a[mf][2] = sA[(rb + g)     * SAS + k0 + t + 4];
            a[mf][3] = sA[(rb + g + 8) * SAS + k0 + t + 4];
        }
        uint32_t b[4][2];
#pragma unroll
        for (int nf = 0; nf < 4; nf++) {
            int cc = wCol + nf * 8 + g;
            b[nf][0] = sW[(k0 + t)     * 132 + cc];
            b[nf][1] = sW[(k0 + t + 4) * 132 + cc];
        }
#pragma unroll
        for (int mf = 0; mf < 2; mf++)
#pragma unroll
            for (int nf = 0; nf < 4; nf++)
                mma_tf32(c[mf][nf], a[mf], b[nf]);
    }
    __syncthreads();

    // stage fragments -> shared
#pragma unroll
    for (int mf = 0; mf < 2; mf++) {
#pragma unroll
        for (int nf = 0; nf < 4; nf++) {
            int ra = wRow + mf * 16 + g;
            int cc = wCol + nf * 8 + t * 2;
            *(float2*)&stage[ra * 132 + cc]       = make_float2(c[mf][nf][0], c[mf][nf][1]);
            *(float2*)&stage[(ra + 8) * 132 + cc] = make_float2(c[mf][nf][2], c[mf][nf][3]);
        }
    }
    __syncthreads();

    // epilogue: warp handles 8 rows; lane owns cols [lane*4, lane*4+4)
    float4 a4 = make_float4(0.f, 0.f, 0.f, 0.f);
    float4 r4 = make_float4(0.f, 0.f, 0.f, 0.f);
    if (lane * 4 < HS * 64) {
        a4 = *(const float4*)&al[lane * 4];
        r4 = *(const float4*)&ar[lane * 4];
    }
#pragma unroll
    for (int q = 0; q < 8; q++) {
        int r = wid * 8 + q;
        int rr = row0 + r;
        float4 f = *(const float4*)&stage[r * 132 + lane * 4];
        // scores
        float sl = f.x * a4.x + f.y * a4.y + f.z * a4.z + f.w * a4.w;
        float sr = f.x * r4.x + f.y * r4.y + f.z * r4.z + f.w * r4.w;
#pragma unroll
        for (int off = 8; off > 0; off >>= 1) {
            sl += __shfl_xor_sync(0xffffffffu, sl, off);
            sr += __shfl_xor_sync(0xffffffffu, sr, off);
        }
        int h = lane >> 4;
        if ((lane & 15) == 0 && h < HS && rr < N) {
            el[rr * HS + h] = sl;
            er[rr * HS + h] = sr;
        }
        // global store
        if (rr < N) {
            if (SPLIT) {
                if (lane < 16) *(float4*)&out [(size_t)rr * 64 + lane * 4]        = f;
                else           *(float4*)&out2[(size_t)rr * 64 + lane * 4 - 64]   = f;
            } else {
                *(float4*)&out[(size_t)rr * 128 + lane * 4] = f;
            }
        }
    }
}

// ---------------------------------------------------------------------------
// Fused aggregation: single-pass softmax, 4-bank MLP accumulation.
// ---------------------------------------------------------------------------
template <int O, int H, bool ELU>
__global__ void __launch_bounds__(256)
k_aggr(const int* __restrict__ row, const int* __restrict__ col,
       const float* __restrict__ el, const float* __restrict__ er,
       const float* __restrict__ fh, const float* __restrict__ bias,
       const float* __restrict__ res, float* __restrict__ out, int N) {
    constexpr int VPT = O / 32;
    const unsigned FULL = 0xffffffffu;
    int w    = (blockIdx.x * blockDim.x + threadIdx.x) >> 5;
    int lane = threadIdx.x & 31;
    if (w >= N) return;
    const bool topHalf = (H == 2) && ((lane * VPT) >= 64);

    const float er0 = er[w * H + 0];
    const float er1 = (H == 2) ? er[w * H + 1] : 0.f;
    const int e0 = row[w], e1 = row[w + 1];

    float den0 = 0.f, den1 = 0.f;
    float acc[4][VPT];
#pragma unroll
    for (int k = 0; k < 4; k++)
#pragma unroll
        for (int i = 0; i < VPT; i++) acc[k][i] = 0.f;

    for (int base = e0; base < e1; base += 32) {
        int idx = base + lane;
        bool valid = idx < e1;
        int s_l = valid ? col[idx] : 0;
        float p0_l = 0.f, p1_l = 0.f;
        if (valid) {
            if (H == 2) {
                float2 ev = *(const float2*)&el[s_l * 2];
                p0_l = __expf(lrelu(ev.x + er0));
                p1_l = __expf(lrelu(ev.y + er1));
                den0 += p0_l; den1 += p1_l;
            } else {
                p0_l = __expf(lrelu(el[s_l] + er0));
                den0 += p0_l;
            }
        }
        int n = min(32, e1 - base);
        int j = 0;
        for (; j + 3 < n; j += 4) {
#pragma unroll
            for (int k = 0; k < 4; k++) {
                int   s  = __shfl_sync(FULL, s_l,  j + k);
                float pa = __shfl_sync(FULL, p0_l, j + k);
                float p;
                if (H == 2) {
                    float pb = __shfl_sync(FULL, p1_l, j + k);
                    p = topHalf ? pb : pa;
                } else p = pa;
                if (VPT == 4) {
                    const float4 f = *(const float4*)&fh[(size_t)s * O + lane * 4];
                    acc[k][0] += p * f.x; acc[k][1] += p * f.y;
                    acc[k][2] += p * f.z; acc[k][3] += p * f.w;
                } else {
                    const float2 f = *(const float2*)&fh[(size_t)s * O + lane * 2];
                    acc[k][0] += p * f.x; acc[k][1] += p * f.y;
                }
            }
        }
        for (; j < n; j++) {
            int   s  = __shfl_sync(FULL, s_l,  j);
            float pa = __shfl_sync(FULL, p0_l, j);
            float p;
            if (H == 2) {
                float pb = __shfl_sync(FULL, p1_l, j);
                p = topHalf ? pb : pa;
            } else p = pa;
            if (VPT == 4) {
                const float4 f = *(const float4*)&fh[(size_t)s * O + lane * 4];
                acc[0][0] += p * f.x; acc[0][1] += p * f.y;
                acc[0][2] += p * f.z; acc[0][3] += p * f.w;
            } else {
                const float2 f = *(const float2*)&fh[(size_t)s * O + lane * 2];
                acc[0][0] += p * f.x; acc[0][1] += p * f.y;
            }
        }
    }

#pragma unroll
    for (int o = 16; o > 0; o >>= 1) {
        den0 += __shfl_xor_sync(FULL, den0, o);
        if (H == 2) den1 += __shfl_xor_sync(FULL, den1, o);
    }
    float den = (H == 2 && topHalf) ? den1 : den0;
    float inv = 1.f / fmaxf(den, 1e-9f);

#pragma unroll
    for (int i = 0; i < VPT; i++) {
        int c = lane * VPT + i;
        float v = (acc[0][i] + acc[1][i] + acc[2][i] + acc[3][i]) * inv + bias[c];
        if (res) v += res[w * O + c];
        if (ELU) v = v > 0.f ? v : (__expf(v) - 1.f);
        out[w * O + c] = v;
    }
}

// ---------------------------------------------------------------------------
extern "C" void kernel_launch(void* const* d_in, const int* in_sizes, int n_in,
                              void* d_out, int out_size) {
    const int*   feats = (const int*)  d_in[0];
    const float* fv    = (const float*)d_in[1];
    const int*   src   = (const int*)  d_in[2];
    const int*   dst   = (const int*)  d_in[3];
    const float* emb   = (const float*)d_in[4];
    const float* W0    = (const float*)d_in[5];
    const float* al0   = (const float*)d_in[6];
    const float* ar0   = (const float*)d_in[7];
    const float* b0    = (const float*)d_in[8];
    const float* W1    = (const float*)d_in[9];
    const float* al1   = (const float*)d_in[10];
    const float* ar1   = (const float*)d_in[11];
    const float* b1    = (const float*)d_in[12];
    const float* W2    = (const float*)d_in[13];
    const float* al2   = (const float*)d_in[14];
    const float* ar2   = (const float*)d_in[15];
    const float* b2    = (const float*)d_in[16];
    const float* resW2 = (const float*)d_in[17];
    float* out = (float*)d_out;

    const int N = in_sizes[0] / 8;
    const int E = in_sizes[2];

    float *hA, *hB, *fh, *el, *er, *Wc;
    int *row, *cur, *col, *bsum;
    cudaGetSymbolAddress((void**)&hA,   g_hA);
    cudaGetSymbolAddress((void**)&hB,   g_hB);
    cudaGetSymbolAddress((void**)&fh,   g_fh);
    cudaGetSymbolAddress((void**)&el,   g_el);
    cudaGetSymbolAddress((void**)&er,   g_er);
    cudaGetSymbolAddress((void**)&Wc,   g_Wc);
    cudaGetSymbolAddress((void**)&row,  g_row);
    cudaGetSymbolAddress((void**)&cur,  g_cur);
    cudaGetSymbolAddress((void**)&col,  g_col);
    cudaGetSymbolAddress((void**)&bsum, g_bsum);

    const int TB = 256;
    const int gB = (N + 63) / 64;
    const int aggrBlocks = (N * 32 + TB - 1) / TB;
    const int nb = (N + 1023) / 1024;

    const int SM64  = 64 * 132 * 4 + 64 * 132 * 4  + 64 * (64 + 4)  * 4;  // 84992
    const int SM128 = 64 * 132 * 4 + 128 * 132 * 4 + 64 * (128 + 4) * 4;  // 135168
    cudaFuncSetAttribute(k_mgemm<64, 2, false>,
                         cudaFuncAttributeMaxDynamicSharedMemorySize, SM64);
    cudaFuncSetAttribute(k_mgemm<128, 2, false>,
                         cudaFuncAttributeMaxDynamicSharedMemorySize, SM128);
    cudaFuncSetAttribute(k_mgemm<128, 1, true>,
                         cudaFuncAttributeMaxDynamicSharedMemorySize, SM128);

    // CSR build
    k_zero   <<<(N + TB - 1) / TB, TB>>>(cur, N);
    k_count  <<<(E + TB - 1) / TB, TB>>>(dst, cur, E);
    k_bsum   <<<nb, 1024>>>(cur, bsum, N);
    k_bscan  <<<1, 32>>>(bsum, nb);
    k_scan2  <<<nb, 1024>>>(cur, bsum, row, cur, N, E);
    k_scatter<<<(E + TB - 1) / TB, TB>>>(src, dst, cur, col, E);

    k_wcat <<<(128 * 128 + TB - 1) / TB, TB>>>(W2, resW2, Wc);
    k_embed<<<(N * 16 + TB - 1) / TB, TB>>>(feats, fv, emb, hA, N);

    // Layer 0: K=64 -> H=2, no residual, ELU, -> hB
    k_mgemm<64, 2, false><<<gB, 256, SM64>>>(hA, W0, fh, nullptr, al0, ar0, el, er, N);
    k_aggr<128, 2, true><<<aggrBlocks, TB>>>(row, col, el, er, fh, b0, nullptr, hB, N);

    // Layer 1: K=128 -> H=2, identity residual, ELU, -> hA
    k_mgemm<128, 2, false><<<gB, 256, SM128>>>(hB, W1, fh, nullptr, al1, ar1, el, er, N);
    k_aggr<128, 2, true><<<aggrBlocks, TB>>>(row, col, el, er, fh, b1, hB, hA, N);

    // Layer 2: combined [W2|resW2]; fh -> cols 0-63, residual -> hB
    k_mgemm<128, 1, true><<<gB, 256, SM128>>>(hA, Wc, fh, hB, al2, ar2, el, er, N);
    k_aggr<64, 1, false><<<aggrBlocks, TB>>>(row, col, el, er, fh, b2, hB, out, N);
}

// round 7
// speedup vs baseline: 3.1790x; 1.1430x over previous
#include <cuda_runtime.h>
#include <cuda_fp16.h>
#include <cstdint>

// ---------------------------------------------------------------------------
// 3-layer GAT, N=50000 nodes, E=800000 edges.
// R7: fp16 fh for layers 0/1 aggregation (half L2 gather traffic),
//     stream-forked CSR build overlapped with embed+GEMM0,
//     parallel block-sum scan. GEMM = mma.sync m16n8k8 tf32.
// ---------------------------------------------------------------------------

#define NMAX 50000
#define EMAX 800000

__device__ float g_hA[NMAX * 128];
__device__ float g_hB[NMAX * 128];
__device__ float g_fh[NMAX * 128];   // fp32 for layer 2; reinterpreted as half for L0/L1
__device__ float g_el[NMAX * 2];
__device__ float g_er[NMAX * 2];
__device__ float g_Wc[128 * 128];
__device__ int   g_row[NMAX + 1];
__device__ int   g_cur[NMAX];
__device__ int   g_col[EMAX];
__device__ int   g_bsum[64];

__device__ __forceinline__ float lrelu(float v) { return v > 0.f ? v : 0.2f * v; }

__device__ __forceinline__ uint32_t f2tf32(float f) {
    uint32_t r;
    asm("cvt.rna.tf32.f32 %0, %1;" : "=r"(r) : "f"(f));
    return r;
}

__device__ __forceinline__ void mma_tf32(float c[4], const uint32_t a[4],
                                         const uint32_t b[2]) {
    asm volatile(
        "mma.sync.aligned.m16n8k8.row.col.f32.tf32.tf32.f32 "
        "{%0,%1,%2,%3}, {%4,%5,%6,%7}, {%8,%9}, {%0,%1,%2,%3};"
        : "+f"(c[0]), "+f"(c[1]), "+f"(c[2]), "+f"(c[3])
        : "r"(a[0]), "r"(a[1]), "r"(a[2]), "r"(a[3]), "r"(b[0]), "r"(b[1]));
}

// Persistent stream/events for capture-legal fork-join (created at load time;
// no device-memory allocation inside kernel_launch).
namespace {
struct ForkRes {
    cudaStream_t s1;
    cudaEvent_t e0, e1;
    ForkRes() {
        cudaStreamCreateWithFlags(&s1, cudaStreamNonBlocking);
        cudaEventCreateWithFlags(&e0, cudaEventDisableTiming);
        cudaEventCreateWithFlags(&e1, cudaEventDisableTiming);
    }
};
ForkRes g_fork;
}

// ---------------------------------------------------------------------------
// Embedding
// ---------------------------------------------------------------------------
__global__ void k_embed(const int* __restrict__ feats, const float* __restrict__ fv,
                        const float* __restrict__ emb, float* __restrict__ h, int N) {
    int i = blockIdx.x * blockDim.x + threadIdx.x;
    if (i >= N * 16) return;
    int n = i >> 4, d4 = i & 15;
    float s = fv[n];
    float4 e = *(const float4*)&emb[(long long)feats[n] * 64 + d4 * 4];
    e.x *= s; e.y *= s; e.z *= s; e.w *= s;
    *(float4*)&h[n * 64 + d4 * 4] = e;
}

// ---------------------------------------------------------------------------
// CSR build
// ---------------------------------------------------------------------------
__global__ void k_zero(int* __restrict__ c, int n) {
    int i = blockIdx.x * blockDim.x + threadIdx.x;
    if (i < n) c[i] = 0;
}
__global__ void k_count(const int* __restrict__ dst, int* __restrict__ cnt, int E) {
    int e = blockIdx.x * blockDim.x + threadIdx.x;
    if (e < E) atomicAdd(&cnt[dst[e]], 1);
}
__global__ void k_bsum(const int* __restrict__ cnt, int* __restrict__ bsum, int N) {
    __shared__ int ws[32];
    int i = blockIdx.x * 1024 + threadIdx.x;
    int lane = threadIdx.x & 31, wid = threadIdx.x >> 5;
    int v = (i < N) ? cnt[i] : 0;
#pragma unroll
    for (int o = 16; o > 0; o >>= 1) v += __shfl_xor_sync(0xffffffffu, v, o);
    if (lane == 0) ws[wid] = v;
    __syncthreads();
    if (wid == 0) {
        int x = ws[lane];
#pragma unroll
        for (int o = 16; o > 0; o >>= 1) x += __shfl_xor_sync(0xffffffffu, x, o);
        if (lane == 0) bsum[blockIdx.x] = x;
    }
}
// parallel exclusive scan over <=64 block sums (one 64-thread block)
__global__ void k_bscan(int* __restrict__ bsum, int nb) {
    __shared__ int sh[64];
    int tid = threadIdx.x;
    int v = (tid < nb) ? bsum[tid] : 0;
    sh[tid] = v;
    __syncthreads();
#pragma unroll
    for (int o = 1; o < 64; o <<= 1) {
        int t = (tid >= o) ? sh[tid - o] : 0;
        __syncthreads();
        sh[tid] += t;
        __syncthreads();
    }
    if (tid < nb) bsum[tid] = sh[tid] - v;
}
__global__ void k_scan2(const int* __restrict__ cnt, const int* __restrict__ bsum,
                        int* __restrict__ row, int* __restrict__ cur, int N, int E) {
    __shared__ int ws[32];
    int i = blockIdx.x * 1024 + threadIdx.x;
    int lane = threadIdx.x & 31, wid = threadIdx.x >> 5;
    int v = (i < N) ? cnt[i] : 0;
    int x = v;
#pragma unroll
    for (int o = 1; o < 32; o <<= 1) {
        int t = __shfl_up_sync(0xffffffffu, x, o);
        if (lane >= o) x += t;
    }
    if (lane == 31) ws[wid] = x;
    __syncthreads();
    if (wid == 0) {
        int y = ws[lane];
#pragma unroll
        for (int o = 1; o < 32; o <<= 1) {
            int t = __shfl_up_sync(0xffffffffu, y, o);
            if (lane >= o) y += t;
        }
        ws[lane] = y;
    }
    __syncthreads();
    int excl = bsum[blockIdx.x] + (wid ? ws[wid - 1] : 0) + x - v;
    if (i < N) { row[i] = excl; cur[i] = excl; }
    if (i == 0) row[N] = E;
}
__global__ void k_scatter(const int* __restrict__ src, const int* __restrict__ dst,
                          int* __restrict__ cur, int* __restrict__ col, int E) {
    int e = blockIdx.x * blockDim.x + threadIdx.x;
    if (e >= E) return;
    int slot = atomicAdd(&cur[dst[e]], 1);
    col[slot] = src[e];
}

// Wc = [W2 | resW2]
__global__ void k_wcat(const float* __restrict__ W2, const float* __restrict__ resW2,
                       float* __restrict__ Wc) {
    int i = blockIdx.x * blockDim.x + threadIdx.x;
    if (i >= 128 * 128) return;
    int k = i >> 7, j = i & 127;
    Wc[i] = (j < 64) ? W2[k * 64 + j] : resW2[k * 64 + (j - 64)];
}

// ---------------------------------------------------------------------------
// TF32 mma.sync GEMM + fused scores. 256 thr, 64 rows x 128 cols per block.
// STOREH: write fh as __half (layers 0/1). SPLIT: cols 0-63 -> out fp32,
// 64-127 -> out2 fp32 (layer 2).
// ---------------------------------------------------------------------------
template <int K, int HS, bool SPLIT, bool STOREH>
__global__ void __launch_bounds__(256)
k_mgemm(const float* __restrict__ A, const float* __restrict__ W,
        float* __restrict__ out, float* __restrict__ out2,
        const float* __restrict__ al, const float* __restrict__ ar,
        float* __restrict__ el, float* __restrict__ er, int N) {
    extern __shared__ char smraw[];
    float*    stage = (float*)smraw;                       // 64*132
    uint32_t* sW    = (uint32_t*)(smraw + 64 * 132 * 4);   // K*132
    uint32_t* sA    = (uint32_t*)(smraw + 64 * 132 * 4 + K * 132 * 4); // 64*(K+4)
    constexpr int SAS = K + 4;

    const int tid = threadIdx.x;
    const int wid = tid >> 5, lane = tid & 31;
    const int g = lane >> 2, t = lane & 3;
    const int row0 = blockIdx.x * 64;
    const int wRow = (wid >> 2) * 32, wCol = (wid & 3) * 32;

    for (int i = tid; i < K * 32; i += 256) {
        int k = i >> 5, c4 = i & 31;
        float4 v = *(const float4*)&W[k * 128 + c4 * 4];
        uint4 u;
        u.x = f2tf32(v.x); u.y = f2tf32(v.y); u.z = f2tf32(v.z); u.w = f2tf32(v.w);
        *(uint4*)&sW[k * 132 + c4 * 4] = u;
    }
    constexpr int C4 = K / 4;
    for (int i = tid; i < 64 * C4; i += 256) {
        int r = i / C4, c4 = i % C4, rr = row0 + r;
        float4 v = make_float4(0.f, 0.f, 0.f, 0.f);
        if (rr < N) v = *(const float4*)&A[(size_t)rr * K + c4 * 4];
        uint4 u;
        u.x = f2tf32(v.x); u.y = f2tf32(v.y); u.z = f2tf32(v.z); u.w = f2tf32(v.w);
        *(uint4*)&sA[r * SAS + c4 * 4] = u;
    }
    __syncthreads();

    float c[2][4][4];
#pragma unroll
    for (int mf = 0; mf < 2; mf++)
#pragma unroll
        for (int nf = 0; nf < 4; nf++)
#pragma unroll
            for (int i = 0; i < 4; i++) c[mf][nf][i] = 0.f;

#pragma unroll
    for (int ks = 0; ks < K / 8; ks++) {
        const int k0 = ks * 8;
        uint32_t a[2][4];
#pragma unroll
        for (int mf = 0; mf < 2; mf++) {
            int rb = wRow + mf * 16;
            a[mf][0] = sA[(rb + g)     * SAS + k0 + t];
            a[mf][1] = sA[(rb + g + 8) * SAS + k0 + t];
            a[mf][2] = sA[(rb + g)     * SAS + k0 + t + 4];
            a[mf][3] = sA[(rb + g + 8) * SAS + k0 + t + 4];
        }
        uint32_t b[4][2];
#pragma unroll
        for (int nf = 0; nf < 4; nf++) {
            int cc = wCol + nf * 8 + g;
            b[nf][0] = sW[(k0 + t)     * 132 + cc];
            b[nf][1] = sW[(k0 + t + 4) * 132 + cc];
        }
#pragma unroll
        for (int mf = 0; mf < 2; mf++)
#pragma unroll
            for (int nf = 0; nf < 4; nf++)
                mma_tf32(c[mf][nf], a[mf], b[nf]);
    }
    __syncthreads();

#pragma unroll
    for (int mf = 0; mf < 2; mf++) {
#pragma unroll
        for (int nf = 0; nf < 4; nf++) {
            int ra = wRow + mf * 16 + g;
            int cc = wCol + nf * 8 + t * 2;
            *(float2*)&stage[ra * 132 + cc]       = make_float2(c[mf][nf][0], c[mf][nf][1]);
            *(float2*)&stage[(ra + 8) * 132 + cc] = make_float2(c[mf][nf][2], c[mf][nf][3]);
        }
    }
    __syncthreads();

    float4 a4 = make_float4(0.f, 0.f, 0.f, 0.f);
    float4 r4 = make_float4(0.f, 0.f, 0.f, 0.f);
    if (lane * 4 < HS * 64) {
        a4 = *(const float4*)&al[lane * 4];
        r4 = *(const float4*)&ar[lane * 4];
    }
#pragma unroll
    for (int q = 0; q < 8; q++) {
        int r = wid * 8 + q;
        int rr = row0 + r;
        float4 f = *(const float4*)&stage[r * 132 + lane * 4];
        float sl = f.x * a4.x + f.y * a4.y + f.z * a4.z + f.w * a4.w;
        float sr = f.x * r4.x + f.y * r4.y + f.z * r4.z + f.w * r4.w;
#pragma unroll
        for (int off = 8; off > 0; off >>= 1) {
            sl += __shfl_xor_sync(0xffffffffu, sl, off);
            sr += __shfl_xor_sync(0xffffffffu, sr, off);
        }
        int h = lane >> 4;
        if ((lane & 15) == 0 && h < HS && rr < N) {
            el[rr * HS + h] = sl;
            er[rr * HS + h] = sr;
        }
        if (rr < N) {
            if (STOREH) {
                __half2 ha = __float22half2_rn(make_float2(f.x, f.y));
                __half2 hb = __float22half2_rn(make_float2(f.z, f.w));
                uint2 u;
                u.x = *(uint32_t*)&ha; u.y = *(uint32_t*)&hb;
                *(uint2*)((__half*)out + (size_t)rr * 128 + lane * 4) = u;
            } else if (SPLIT) {
                if (lane < 16) *(float4*)&out [(size_t)rr * 64 + lane * 4]      = f;
                else           *(float4*)&out2[(size_t)rr * 64 + lane * 4 - 64] = f;
            } else {
                *(float4*)&out[(size_t)rr * 128 + lane * 4] = f;
            }
        }
    }
}

// ---------------------------------------------------------------------------
// Fused aggregation: single-pass softmax, 4-bank MLP accumulation.
// HALFIN: fh stored as __half (layers 0/1).
// ---------------------------------------------------------------------------
template <int O, int H, bool ELU, bool HALFIN>
__global__ void __launch_bounds__(256)
k_aggr(const int* __restrict__ row, const int* __restrict__ col,
       const float* __restrict__ el, const float* __restrict__ er,
       const void* __restrict__ fhv, const float* __restrict__ bias,
       const float* __restrict__ res, float* __restrict__ out, int N) {
    constexpr int VPT = O / 32;
    const unsigned FULL = 0xffffffffu;
    int w    = (blockIdx.x * blockDim.x + threadIdx.x) >> 5;
    int lane = threadIdx.x & 31;
    if (w >= N) return;
    const bool topHalf = (H == 2) && ((lane * VPT) >= 64);
    const float* fhf = (const float*)fhv;
    const __half* fhh = (const __half*)fhv;

    const float er0 = er[w * H + 0];
    const float er1 = (H == 2) ? er[w * H + 1] : 0.f;
    const int e0 = row[w], e1 = row[w + 1];

    float den0 = 0.f, den1 = 0.f;
    float acc[4][VPT];
#pragma unroll
    for (int k = 0; k < 4; k++)
#pragma unroll
        for (int i = 0; i < VPT; i++) acc[k][i] = 0.f;

    for (int base = e0; base < e1; base += 32) {
        int idx = base + lane;
        bool valid = idx < e1;
        int s_l = valid ? col[idx] : 0;
        float p0_l = 0.f, p1_l = 0.f;
        if (valid) {
            if (H == 2) {
                float2 ev = *(const float2*)&el[s_l * 2];
                p0_l = __expf(lrelu(ev.x + er0));
                p1_l = __expf(lrelu(ev.y + er1));
                den0 += p0_l; den1 += p1_l;
            } else {
                p0_l = __expf(lrelu(el[s_l] + er0));
                den0 += p0_l;
            }
        }
        int n = min(32, e1 - base);
        int j = 0;
        for (; j + 3 < n; j += 4) {
#pragma unroll
            for (int k = 0; k < 4; k++) {
                int   s  = __shfl_sync(FULL, s_l,  j + k);
                float pa = __shfl_sync(FULL, p0_l, j + k);
                float p;
                if (H == 2) {
                    float pb = __shfl_sync(FULL, p1_l, j + k);
                    p = topHalf ? pb : pa;
                } else p = pa;
                if (HALFIN) {
                    uint2 u = *(const uint2*)(fhh + (size_t)s * O + lane * 4);
                    float2 lo = __half22float2(*(__half2*)&u.x);
                    float2 hi = __half22float2(*(__half2*)&u.y);
                    acc[k][0] += p * lo.x; acc[k][1] += p * lo.y;
                    acc[k][2] += p * hi.x; acc[k][3] += p * hi.y;
                } else if (VPT == 4) {
                    const float4 f = *(const float4*)&fhf[(size_t)s * O + lane * 4];
                    acc[k][0] += p * f.x; acc[k][1] += p * f.y;
                    acc[k][2] += p * f.z; acc[k][3] += p * f.w;
                } else {
                    const float2 f = *(const float2*)&fhf[(size_t)s * O + lane * 2];
                    acc[k][0] += p * f.x; acc[k][1] += p * f.y;
                }
            }
        }
        for (; j < n; j++) {
            int   s  = __shfl_sync(FULL, s_l,  j);
            float pa = __shfl_sync(FULL, p0_l, j);
            float p;
            if (H == 2) {
                float pb = __shfl_sync(FULL, p1_l, j);
                p = topHalf ? pb : pa;
            } else p = pa;
            if (HALFIN) {
                uint2 u = *(const uint2*)(fhh + (size_t)s * O + lane * 4);
                float2 lo = __half22float2(*(__half2*)&u.x);
                float2 hi = __half22float2(*(__half2*)&u.y);
                acc[0][0] += p * lo.x; acc[0][1] += p * lo.y;
                acc[0][2] += p * hi.x; acc[0][3] += p * hi.y;
            } else if (VPT == 4) {
                const float4 f = *(const float4*)&fhf[(size_t)s * O + lane * 4];
                acc[0][0] += p * f.x; acc[0][1] += p * f.y;
                acc[0][2] += p * f.z; acc[0][3] += p * f.w;
            } else {
                const float2 f = *(const float2*)&fhf[(size_t)s * O + lane * 2];
                acc[0][0] += p * f.x; acc[0][1] += p * f.y;
            }
        }
    }

#pragma unroll
    for (int o = 16; o > 0; o >>= 1) {
        den0 += __shfl_xor_sync(FULL, den0, o);
        if (H == 2) den1 += __shfl_xor_sync(FULL, den1, o);
    }
    float den = (H == 2 && topHalf) ? den1 : den0;
    float inv = 1.f / fmaxf(den, 1e-9f);

#pragma unroll
    for (int i = 0; i < VPT; i++) {
        int c = lane * VPT + i;
        float v = (acc[0][i] + acc[1][i] + acc[2][i] + acc[3][i]) * inv + bias[c];
        if (res) v += res[w * O + c];
        if (ELU) v = v > 0.f ? v : (__expf(v) - 1.f);
        out[w * O + c] = v;
    }
}

// ---------------------------------------------------------------------------
extern "C" void kernel_launch(void* const* d_in, const int* in_sizes, int n_in,
                              void* d_out, int out_size) {
    const int*   feats = (const int*)  d_in[0];
    const float* fv    = (const float*)d_in[1];
    const int*   src   = (const int*)  d_in[2];
    const int*   dst   = (const int*)  d_in[3];
    const float* emb   = (const float*)d_in[4];
    const float* W0    = (const float*)d_in[5];
    const float* al0   = (const float*)d_in[6];
    const float* ar0   = (const float*)d_in[7];
    const float* b0    = (const float*)d_in[8];
    const float* W1    = (const float*)d_in[9];
    const float* al1   = (const float*)d_in[10];
    const float* ar1   = (const float*)d_in[11];
    const float* b1    = (const float*)d_in[12];
    const float* W2    = (const float*)d_in[13];
    const float* al2   = (const float*)d_in[14];
    const float* ar2   = (const float*)d_in[15];
    const float* b2    = (const float*)d_in[16];
    const float* resW2 = (const float*)d_in[17];
    float* out = (float*)d_out;

    const int N = in_sizes[0] / 8;
    const int E = in_sizes[2];

    float *hA, *hB, *fh, *el, *er, *Wc;
    int *row, *cur, *col, *bsum;
    cudaGetSymbolAddress((void**)&hA,   g_hA);
    cudaGetSymbolAddress((void**)&hB,   g_hB);
    cudaGetSymbolAddress((void**)&fh,   g_fh);
    cudaGetSymbolAddress((void**)&el,   g_el);
    cudaGetSymbolAddress((void**)&er,   g_er);
    cudaGetSymbolAddress((void**)&Wc,   g_Wc);
    cudaGetSymbolAddress((void**)&row,  g_row);
    cudaGetSymbolAddress((void**)&cur,  g_cur);
    cudaGetSymbolAddress((void**)&col,  g_col);
    cudaGetSymbolAddress((void**)&bsum, g_bsum);

    const int TB = 256;
    const int gB = (N + 63) / 64;
    const int aggrBlocks = (N * 32 + TB - 1) / TB;
    const int nb = (N + 1023) / 1024;

    const int SM64  = 64 * 132 * 4 + 64 * 132 * 4  + 64 * (64 + 4)  * 4;
    const int SM128 = 64 * 132 * 4 + 128 * 132 * 4 + 64 * (128 + 4) * 4;
    cudaFuncSetAttribute(k_mgemm<64, 2, false, true>,
                         cudaFuncAttributeMaxDynamicSharedMemorySize, SM64);
    cudaFuncSetAttribute(k_mgemm<128, 2, false, true>,
                         cudaFuncAttributeMaxDynamicSharedMemorySize, SM128);
    cudaFuncSetAttribute(k_mgemm<128, 1, true, false>,
                         cudaFuncAttributeMaxDynamicSharedMemorySize, SM128);

    cudaStream_t s1 = g_fork.s1;

    // fork: CSR build + wcat on s1, embedding + GEMM0 on main stream
    cudaEventRecord(g_fork.e0, 0);
    cudaStreamWaitEvent(s1, g_fork.e0, 0);

    k_zero   <<<(N + TB - 1) / TB, TB, 0, s1>>>(cur, N);
    k_count  <<<(E + TB - 1) / TB, TB, 0, s1>>>(dst, cur, E);
    k_bsum   <<<nb, 1024, 0, s1>>>(cur, bsum, N);
    k_bscan  <<<1, 64, 0, s1>>>(bsum, nb);
    k_scan2  <<<nb, 1024, 0, s1>>>(cur, bsum, row, cur, N, E);
    k_scatter<<<(E + TB - 1) / TB, TB, 0, s1>>>(src, dst, cur, col, E);
    k_wcat   <<<(128 * 128 + TB - 1) / TB, TB, 0, s1>>>(W2, resW2, Wc);
    cudaEventRecord(g_fork.e1, s1);

    k_embed<<<(N * 16 + TB - 1) / TB, TB>>>(feats, fv, emb, hA, N);
    k_mgemm<64, 2, false, true><<<gB, 256, SM64>>>(hA, W0, fh, nullptr, al0, ar0, el, er, N);

    // join before first aggregation
    cudaStreamWaitEvent(0, g_fork.e1, 0);

    // Layer 0: fh half, no residual, ELU, -> hB
    k_aggr<128, 2, true, true><<<aggrBlocks, TB>>>(row, col, el, er, fh, b0, nullptr, hB, N);

    // Layer 1: fh half, identity residual, ELU, -> hA
    k_mgemm<128, 2, false, true><<<gB, 256, SM128>>>(hB, W1, fh, nullptr, al1, ar1, el, er, N);
    k_aggr<128, 2, true, true><<<aggrBlocks, TB>>>(row, col, el, er, fh, b1, hB, hA, N);

    // Layer 2: fp32; combined [W2|resW2] -> fh (cols 0-63) + residual hB
    k_mgemm<128, 1, true, false><<<gB, 256, SM128>>>(hA, Wc, fh, hB, al2, ar2, el, er, N);
    k_aggr<64, 1, false, false><<<aggrBlocks, TB>>>(row, col, el, er, fh, b2, hB, out, N);
}

// round 8
// speedup vs baseline: 3.2941x; 1.0362x over previous
#include <cuda_runtime.h>
#include <cuda_fp16.h>
#include <cstdint>

// ---------------------------------------------------------------------------
// 3-layer GAT, N=50000 nodes, E=800000 edges.
// R8: parallel-edge fp16 aggregation (G edges/warp-step, uint4 loads),
//     fp16 fh for all 3 layers, embedding fused into GEMM0 A-loader,
//     stream-forked CSR build. GEMM = mma.sync m16n8k8 tf32.
// ---------------------------------------------------------------------------

#define NMAX 50000
#define EMAX 800000

__device__ float g_hA[NMAX * 128];
__device__ float g_hB[NMAX * 128];
__device__ float g_fh[NMAX * 128];   // used as __half[NMAX*128]
__device__ float g_el[NMAX * 2];
__device__ float g_er[NMAX * 2];
__device__ float g_Wc[128 * 128];
__device__ int   g_row[NMAX + 1];
__device__ int   g_cur[NMAX];
__device__ int   g_col[EMAX];
__device__ int   g_bsum[64];

__device__ __forceinline__ float lrelu(float v) { return v > 0.f ? v : 0.2f * v; }

__device__ __forceinline__ uint32_t f2tf32(float f) {
    uint32_t r;
    asm("cvt.rna.tf32.f32 %0, %1;" : "=r"(r) : "f"(f));
    return r;
}

__device__ __forceinline__ void mma_tf32(float c[4], const uint32_t a[4],
                                         const uint32_t b[2]) {
    asm volatile(
        "mma.sync.aligned.m16n8k8.row.col.f32.tf32.tf32.f32 "
        "{%0,%1,%2,%3}, {%4,%5,%6,%7}, {%8,%9}, {%0,%1,%2,%3};"
        : "+f"(c[0]), "+f"(c[1]), "+f"(c[2]), "+f"(c[3])
        : "r"(a[0]), "r"(a[1]), "r"(a[2]), "r"(a[3]), "r"(b[0]), "r"(b[1]));
}

namespace {
struct ForkRes {
    cudaStream_t s1;
    cudaEvent_t e0, e1;
    ForkRes() {
        cudaStreamCreateWithFlags(&s1, cudaStreamNonBlocking);
        cudaEventCreateWithFlags(&e0, cudaEventDisableTiming);
        cudaEventCreateWithFlags(&e1, cudaEventDisableTiming);
    }
};
ForkRes g_fork;
}

// ---------------------------------------------------------------------------
// CSR build
// ---------------------------------------------------------------------------
__global__ void k_zero(int* __restrict__ c, int n) {
    int i = blockIdx.x * blockDim.x + threadIdx.x;
    if (i < n) c[i] = 0;
}
__global__ void k_count(const int* __restrict__ dst, int* __restrict__ cnt, int E) {
    int e = blockIdx.x * blockDim.x + threadIdx.x;
    if (e < E) atomicAdd(&cnt[dst[e]], 1);
}
__global__ void k_bsum(const int* __restrict__ cnt, int* __restrict__ bsum, int N) {
    __shared__ int ws[32];
    int i = blockIdx.x * 1024 + threadIdx.x;
    int lane = threadIdx.x & 31, wid = threadIdx.x >> 5;
    int v = (i < N) ? cnt[i] : 0;
#pragma unroll
    for (int o = 16; o > 0; o >>= 1) v += __shfl_xor_sync(0xffffffffu, v, o);
    if (lane == 0) ws[wid] = v;
    __syncthreads();
    if (wid == 0) {
        int x = ws[lane];
#pragma unroll
        for (int o = 16; o > 0; o >>= 1) x += __shfl_xor_sync(0xffffffffu, x, o);
        if (lane == 0) bsum[blockIdx.x] = x;
    }
}
__global__ void k_bscan(int* __restrict__ bsum, int nb) {
    __shared__ int sh[64];
    int tid = threadIdx.x;
    int v = (tid < nb) ? bsum[tid] : 0;
    sh[tid] = v;
    __syncthreads();
#pragma unroll
    for (int o = 1; o < 64; o <<= 1) {
        int t = (tid >= o) ? sh[tid - o] : 0;
        __syncthreads();
        sh[tid] += t;
        __syncthreads();
    }
    if (tid < nb) bsum[tid] = sh[tid] - v;
}
__global__ void k_scan2(const int* __restrict__ cnt, const int* __restrict__ bsum,
                        int* __restrict__ row, int* __restrict__ cur, int N, int E) {
    __shared__ int ws[32];
    int i = blockIdx.x * 1024 + threadIdx.x;
    int lane = threadIdx.x & 31, wid = threadIdx.x >> 5;
    int v = (i < N) ? cnt[i] : 0;
    int x = v;
#pragma unroll
    for (int o = 1; o < 32; o <<= 1) {
        int t = __shfl_up_sync(0xffffffffu, x, o);
        if (lane >= o) x += t;
    }
    if (lane == 31) ws[wid] = x;
    __syncthreads();
    if (wid == 0) {
        int y = ws[lane];
#pragma unroll
        for (int o = 1; o < 32; o <<= 1) {
            int t = __shfl_up_sync(0xffffffffu, y, o);
            if (lane >= o) y += t;
        }
        ws[lane] = y;
    }
    __syncthreads();
    int excl = bsum[blockIdx.x] + (wid ? ws[wid - 1] : 0) + x - v;
    if (i < N) { row[i] = excl; cur[i] = excl; }
    if (i == 0) row[N] = E;
}
__global__ void k_scatter(const int* __restrict__ src, const int* __restrict__ dst,
                          int* __restrict__ cur, int* __restrict__ col, int E) {
    int e = blockIdx.x * blockDim.x + threadIdx.x;
    if (e >= E) return;
    int slot = atomicAdd(&cur[dst[e]], 1);
    col[slot] = src[e];
}
__global__ void k_wcat(const float* __restrict__ W2, const float* __restrict__ resW2,
                       float* __restrict__ Wc) {
    int i = blockIdx.x * blockDim.x + threadIdx.x;
    if (i >= 128 * 128) return;
    int k = i >> 7, j = i & 127;
    Wc[i] = (j < 64) ? W2[k * 64 + j] : resW2[k * 64 + (j - 64)];
}

// ---------------------------------------------------------------------------
// TF32 mma.sync GEMM + fused scores. 256 thr, 64 rows x 128 cols per block.
// EMB: A-tile gathered from emb[feats[n]]*fv[n] (layer 0).
// STOREH: fh stored as half. SPLIT: cols 0-63 -> out(half), 64-127 -> out2(f32).
// ---------------------------------------------------------------------------
template <int K, int HS, bool SPLIT, bool EMB>
__global__ void __launch_bounds__(256)
k_mgemm(const float* __restrict__ A, const int* __restrict__ feats,
        const float* __restrict__ fv, const float* __restrict__ emb,
        const float* __restrict__ W,
        void* __restrict__ outh, float* __restrict__ out2,
        const float* __restrict__ al, const float* __restrict__ ar,
        float* __restrict__ el, float* __restrict__ er, int N) {
    extern __shared__ char smraw[];
    float*    stage = (float*)smraw;                       // 64*132
    uint32_t* sW    = (uint32_t*)(smraw + 64 * 132 * 4);   // K*132
    uint32_t* sA    = (uint32_t*)(smraw + 64 * 132 * 4 + K * 132 * 4); // 64*(K+4)
    constexpr int SAS = K + 4;

    const int tid = threadIdx.x;
    const int wid = tid >> 5, lane = tid & 31;
    const int g = lane >> 2, t = lane & 3;
    const int row0 = blockIdx.x * 64;
    const int wRow = (wid >> 2) * 32, wCol = (wid & 3) * 32;

    for (int i = tid; i < K * 32; i += 256) {
        int k = i >> 5, c4 = i & 31;
        float4 v = *(const float4*)&W[k * 128 + c4 * 4];
        uint4 u;
        u.x = f2tf32(v.x); u.y = f2tf32(v.y); u.z = f2tf32(v.z); u.w = f2tf32(v.w);
        *(uint4*)&sW[k * 132 + c4 * 4] = u;
    }
    constexpr int C4 = K / 4;
    for (int i = tid; i < 64 * C4; i += 256) {
        int r = i / C4, c4 = i % C4, rr = row0 + r;
        float4 v = make_float4(0.f, 0.f, 0.f, 0.f);
        if (rr < N) {
            if (EMB) {
                float s = fv[rr];
                v = *(const float4*)&emb[(long long)feats[rr] * 64 + c4 * 4];
                v.x *= s; v.y *= s; v.z *= s; v.w *= s;
            } else {
                v = *(const float4*)&A[(size_t)rr * K + c4 * 4];
            }
        }
        uint4 u;
        u.x = f2tf32(v.x); u.y = f2tf32(v.y); u.z = f2tf32(v.z); u.w = f2tf32(v.w);
        *(uint4*)&sA[r * SAS + c4 * 4] = u;
    }
    __syncthreads();

    float c[2][4][4];
#pragma unroll
    for (int mf = 0; mf < 2; mf++)
#pragma unroll
        for (int nf = 0; nf < 4; nf++)
#pragma unroll
            for (int i = 0; i < 4; i++) c[mf][nf][i] = 0.f;

#pragma unroll
    for (int ks = 0; ks < K / 8; ks++) {
        const int k0 = ks * 8;
        uint32_t a[2][4];
#pragma unroll
        for (int mf = 0; mf < 2; mf++) {
            int rb = wRow + mf * 16;
            a[mf][0] = sA[(rb + g)     * SAS + k0 + t];
            a[mf][1] = sA[(rb + g + 8) * SAS + k0 + t];
            a[mf][2] = sA[(rb + g)     * SAS + k0 + t + 4];
            a[mf][3] = sA[(rb + g + 8) * SAS + k0 + t + 4];
        }
        uint32_t b[4][2];
#pragma unroll
        for (int nf = 0; nf < 4; nf++) {
            int cc = wCol + nf * 8 + g;
            b[nf][0] = sW[(k0 + t)     * 132 + cc];
            b[nf][1] = sW[(k0 + t + 4) * 132 + cc];
        }
#pragma unroll
        for (int mf = 0; mf < 2; mf++)
#pragma unroll
            for (int nf = 0; nf < 4; nf++)
                mma_tf32(c[mf][nf], a[mf], b[nf]);
    }
    __syncthreads();

#pragma unroll
    for (int mf = 0; mf < 2; mf++) {
#pragma unroll
        for (int nf = 0; nf < 4; nf++) {
            int ra = wRow + mf * 16 + g;
            int cc = wCol + nf * 8 + t * 2;
            *(float2*)&stage[ra * 132 + cc]       = make_float2(c[mf][nf][0], c[mf][nf][1]);
            *(float2*)&stage[(ra + 8) * 132 + cc] = make_float2(c[mf][nf][2], c[mf][nf][3]);
        }
    }
    __syncthreads();

    float4 a4 = make_float4(0.f, 0.f, 0.f, 0.f);
    float4 r4 = make_float4(0.f, 0.f, 0.f, 0.f);
    if (lane * 4 < HS * 64) {
        a4 = *(const float4*)&al[lane * 4];
        r4 = *(const float4*)&ar[lane * 4];
    }
    __half* fhh = (__half*)outh;
#pragma unroll
    for (int q = 0; q < 8; q++) {
        int r = wid * 8 + q;
        int rr = row0 + r;
        float4 f = *(const float4*)&stage[r * 132 + lane * 4];
        float sl = f.x * a4.x + f.y * a4.y + f.z * a4.z + f.w * a4.w;
        float sr = f.x * r4.x + f.y * r4.y + f.z * r4.z + f.w * r4.w;
#pragma unroll
        for (int off = 8; off > 0; off >>= 1) {
            sl += __shfl_xor_sync(0xffffffffu, sl, off);
            sr += __shfl_xor_sync(0xffffffffu, sr, off);
        }
        int h = lane >> 4;
        if ((lane & 15) == 0 && h < HS && rr < N) {
            el[rr * HS + h] = sl;
            er[rr * HS + h] = sr;
        }
        if (rr < N) {
            __half2 ha = __float22half2_rn(make_float2(f.x, f.y));
            __half2 hb = __float22half2_rn(make_float2(f.z, f.w));
            uint2 u;
            u.x = *(uint32_t*)&ha; u.y = *(uint32_t*)&hb;
            if (SPLIT) {
                if (lane < 16) *(uint2*)(fhh + (size_t)rr * 64 + lane * 4) = u;
                else           *(float4*)&out2[(size_t)rr * 64 + lane * 4 - 64] = f;
            } else {
                *(uint2*)(fhh + (size_t)rr * 128 + lane * 4) = u;
            }
        }
    }
}

// ---------------------------------------------------------------------------
// Parallel-edge fp16 aggregation. One warp per dst node.
// Row = O halves = 2*O bytes; L = O/8 lanes per row (uint4 = 8 halves each);
// G = 32/L edges processed in parallel per step; 2 banks -> 2G edges in flight.
// ---------------------------------------------------------------------------
template <int O, int H, bool ELU>
__global__ void __launch_bounds__(256)
k_aggr(const int* __restrict__ row, const int* __restrict__ col,
       const float* __restrict__ el, const float* __restrict__ er,
       const void* __restrict__ fhv, const float* __restrict__ bias,
       const float* __restrict__ res, float* __restrict__ out, int N) {
    constexpr int L = O / 8;     // 16 (O=128) or 8 (O=64)
    constexpr int G = 32 / L;    // 2 or 4
    const unsigned FULL = 0xffffffffu;
    int w    = (blockIdx.x * blockDim.x + threadIdx.x) >> 5;
    int lane = threadIdx.x & 31;
    if (w >= N) return;
    const int grp = lane / L, sub = lane % L;
    const int c0 = sub * 8;
    const bool topHead = (H == 2) && (c0 >= 64);
    const __half* fhh = (const __half*)fhv;

    const float er0 = er[w * H + 0];
    const float er1 = (H == 2) ? er[w * H + 1] : 0.f;
    const int e0 = row[w], e1 = row[w + 1];

    float den0 = 0.f, den1 = 0.f;
    float acc[2][8];
#pragma unroll
    for (int b = 0; b < 2; b++)
#pragma unroll
        for (int i = 0; i < 8; i++) acc[b][i] = 0.f;

    for (int base = e0; base < e1; base += 32) {
        int idx = base + lane;
        bool valid = idx < e1;
        int s_l = valid ? col[idx] : 0;
        float p0_l = 0.f, p1_l = 0.f;
        if (valid) {
            if (H == 2) {
                float2 ev = *(const float2*)&el[s_l * 2];
                p0_l = __expf(lrelu(ev.x + er0));
                p1_l = __expf(lrelu(ev.y + er1));
                den0 += p0_l; den1 += p1_l;
            } else {
                p0_l = __expf(lrelu(el[s_l] + er0));
                den0 += p0_l;
            }
        }
        int n = min(32, e1 - base);
        for (int j = 0; j < n; j += 2 * G) {
#pragma unroll
            for (int b = 0; b < 2; b++) {
                int srcLane = j + b * G + grp;           // <= 31 by construction
                int   s  = __shfl_sync(FULL, s_l,  srcLane);
                float pa = __shfl_sync(FULL, p0_l, srcLane);
                float p;
                if (H == 2) {
                    float pb = __shfl_sync(FULL, p1_l, srcLane);
                    p = topHead ? pb : pa;
                } else p = pa;
                uint4 u = *(const uint4*)(fhh + (size_t)s * O + c0);
                float2 f0 = __half22float2(*(__half2*)&u.x);
                float2 f1 = __half22float2(*(__half2*)&u.y);
                float2 f2 = __half22float2(*(__half2*)&u.z);
                float2 f3 = __half22float2(*(__half2*)&u.w);
                acc[b][0] += p * f0.x; acc[b][1] += p * f0.y;
                acc[b][2] += p * f1.x; acc[b][3] += p * f1.y;
                acc[b][4] += p * f2.x; acc[b][5] += p * f2.y;
                acc[b][6] += p * f3.x; acc[b][7] += p * f3.y;
            }
        }
    }

    // reduce den over warp
#pragma unroll
    for (int o = 16; o > 0; o >>= 1) {
        den0 += __shfl_xor_sync(FULL, den0, o);
        if (H == 2) den1 += __shfl_xor_sync(FULL, den1, o);
    }
    // combine edge groups (lanes differing by multiples of L)
    float sum[8];
#pragma unroll
    for (int i = 0; i < 8; i++) {
        float v = acc[0][i] + acc[1][i];
#pragma unroll
        for (int o = L; o < 32; o <<= 1) v += __shfl_xor_sync(FULL, v, o);
        sum[i] = v;
    }

    if (grp == 0) {
        float den = topHead ? den1 : den0;
        float inv = 1.f / fmaxf(den, 1e-9f);
        float4 bva = *(const float4*)&bias[c0];
        float4 bvb = *(const float4*)&bias[c0 + 4];
        float4 ra = make_float4(0.f, 0.f, 0.f, 0.f), rb = ra;
        if (res) {
            ra = *(const float4*)&res[(size_t)w * O + c0];
            rb = *(const float4*)&res[(size_t)w * O + c0 + 4];
        }
        float o8[8];
        o8[0] = sum[0] * inv + bva.x + ra.x;
        o8[1] = sum[1] * inv + bva.y + ra.y;
        o8[2] = sum[2] * inv + bva.z + ra.z;
        o8[3] = sum[3] * inv + bva.w + ra.w;
        o8[4] = sum[4] * inv + bvb.x + rb.x;
        o8[5] = sum[5] * inv + bvb.y + rb.y;
        o8[6] = sum[6] * inv + bvb.z + rb.z;
        o8[7] = sum[7] * inv + bvb.w + rb.w;
        if (ELU) {
#pragma unroll
            for (int i = 0; i < 8; i++)
                o8[i] = o8[i] > 0.f ? o8[i] : (__expf(o8[i]) - 1.f);
        }
        *(float4*)&out[(size_t)w * O + c0]     = make_float4(o8[0], o8[1], o8[2], o8[3]);
        *(float4*)&out[(size_t)w * O + c0 + 4] = make_float4(o8[4], o8[5], o8[6], o8[7]);
    }
}

// ---------------------------------------------------------------------------
extern "C" void kernel_launch(void* const* d_in, const int* in_sizes, int n_in,
                              void* d_out, int out_size) {
    const int*   feats = (const int*)  d_in[0];
    const float* fv    = (const float*)d_in[1];
    const int*   src   = (const int*)  d_in[2];
    const int*   dst   = (const int*)  d_in[3];
    const float* emb   = (const float*)d_in[4];
    const float* W0    = (const float*)d_in[5];
    const float* al0   = (const float*)d_in[6];
    const float* ar0   = (const float*)d_in[7];
    const float* b0    = (const float*)d_in[8];
    const float* W1    = (const float*)d_in[9];
    const float* al1   = (const float*)d_in[10];
    const float* ar1   = (const float*)d_in[11];
    const float* b1    = (const float*)d_in[12];
    const float* W2    = (const float*)d_in[13];
    const float* al2   = (const float*)d_in[14];
    const float* ar2   = (const float*)d_in[15];
    const float* b2    = (const float*)d_in[16];
    const float* resW2 = (const float*)d_in[17];
    float* out = (float*)d_out;

    const int N = in_sizes[0] / 8;
    const int E = in_sizes[2];

    float *hA, *hB, *fh, *el, *er, *Wc;
    int *row, *cur, *col, *bsum;
    cudaGetSymbolAddress((void**)&hA,   g_hA);
    cudaGetSymbolAddress((void**)&hB,   g_hB);
    cudaGetSymbolAddress((void**)&fh,   g_fh);
    cudaGetSymbolAddress((void**)&el,   g_el);
    cudaGetSymbolAddress((void**)&er,   g_er);
    cudaGetSymbolAddress((void**)&Wc,   g_Wc);
    cudaGetSymbolAddress((void**)&row,  g_row);
    cudaGetSymbolAddress((void**)&cur,  g_cur);
    cudaGetSymbolAddress((void**)&col,  g_col);
    cudaGetSymbolAddress((void**)&bsum, g_bsum);

    const int TB = 256;
    const int gB = (N + 63) / 64;
    const int aggrBlocks = (N * 32 + TB - 1) / TB;
    const int nb = (N + 1023) / 1024;

    const int SM64  = 64 * 132 * 4 + 64 * 132 * 4  + 64 * (64 + 4)  * 4;
    const int SM128 = 64 * 132 * 4 + 128 * 132 * 4 + 64 * (128 + 4) * 4;
    cudaFuncSetAttribute(k_mgemm<64, 2, false, true>,
                         cudaFuncAttributeMaxDynamicSharedMemorySize, SM64);
    cudaFuncSetAttribute(k_mgemm<128, 2, false, false>,
                         cudaFuncAttributeMaxDynamicSharedMemorySize, SM128);
    cudaFuncSetAttribute(k_mgemm<128, 1, true, false>,
                         cudaFuncAttributeMaxDynamicSharedMemorySize, SM128);

    cudaStream_t s1 = g_fork.s1;

    // fork: CSR build + wcat on s1; GEMM0 (with fused embedding) on main
    cudaEventRecord(g_fork.e0, 0);
    cudaStreamWaitEvent(s1, g_fork.e0, 0);

    k_zero   <<<(N + TB - 1) / TB, TB, 0, s1>>>(cur, N);
    k_count  <<<(E + TB - 1) / TB, TB, 0, s1>>>(dst, cur, E);
    k_bsum   <<<nb, 1024, 0, s1>>>(cur, bsum, N);
    k_bscan  <<<1, 64, 0, s1>>>(bsum, nb);
    k_scan2  <<<nb, 1024, 0, s1>>>(cur, bsum, row, cur, N, E);
    k_scatter<<<(E + TB - 1) / TB, TB, 0, s1>>>(src, dst, cur, col, E);
    k_wcat   <<<(128 * 128 + TB - 1) / TB, TB, 0, s1>>>(W2, resW2, Wc);
    cudaEventRecord(g_fork.e1, s1);

    // Layer 0 GEMM with fused embedding
    k_mgemm<64, 2, false, true><<<gB, 256, SM64>>>(
        nullptr, feats, fv, emb, W0, fh, nullptr, al0, ar0, el, er, N);

    cudaStreamWaitEvent(0, g_fork.e1, 0);

    // Layer 0 aggregation -> hB (fp32)
    k_aggr<128, 2, true><<<aggrBlocks, TB>>>(row, col, el, er, fh, b0, nullptr, hB, N);

    // Layer 1
    k_mgemm<128, 2, false, false><<<gB, 256, SM128>>>(
        hB, nullptr, nullptr, nullptr, W1, fh, nullptr, al1, ar1, el, er, N);
    k_aggr<128, 2, true><<<aggrBlocks, TB>>>(row, col, el, er, fh, b1, hB, hA, N);

    // Layer 2: combined [W2|resW2]; fh(half, cols 0-63) + residual hB(f32)
    k_mgemm<128, 1, true, false><<<gB, 256, SM128>>>(
        hA, nullptr, nullptr, nullptr, Wc, fh, hB, al2, ar2, el, er, N);
    k_aggr<64, 1, false><<<aggrBlocks, TB>>>(row, col, el, er, fh, b2, hB, out, N);
}